// round 1
// baseline (speedup 1.0000x reference)
#include <cuda_runtime.h>
#include <cuda_bf16.h>

// Problem constants (fixed by the dataset)
#define Bq   2
#define Sq   2048
#define Hd   2048
#define HQn  16
#define HKVn 4
#define Dh   128
#define NREP (HQn / HKVn)

// Scratch (device globals; no runtime allocation allowed)
__device__ float g_q[(size_t)Bq * Sq * HQn * Dh];    // 32 MB
__device__ float g_k[(size_t)Bq * Sq * HKVn * Dh];   // 8 MB
__device__ float g_v[(size_t)Bq * Sq * HKVn * Dh];   // 8 MB
__device__ float g_ctx[(size_t)Bq * Sq * HQn * Dh];  // 32 MB

// ---------------------------------------------------------------------------
// SGEMM: C[M,N] = A[M,K] @ B[K,N], all row-major fp32.
// 128x128 block tile, BK=16, 8x8 per thread, 256 threads.
// All of M,N,K are multiples of 128 here, so no edge guards.
// ---------------------------------------------------------------------------
template <int BM, int BN, int BK, int TM, int TN>
__global__ void __launch_bounds__(256, 1)
sgemm_kernel(int M, int N, int K,
             const float* __restrict__ A,
             const float* __restrict__ B,
             float* __restrict__ C) {
    __shared__ float As[BK][BM];        // stored transposed
    __shared__ float Bs[BK][BN + 4];    // +4 pad keeps 16B alignment, cuts conflicts

    const int tid = threadIdx.x;
    const int tr  = tid / (BN / TN);    // 0..15
    const int tc  = tid % (BN / TN);    // 0..15

    const float* Ab = A + (size_t)blockIdx.y * BM * K;
    const float* Bb = B + (size_t)blockIdx.x * BN;

    float acc[TM][TN];
#pragma unroll
    for (int m = 0; m < TM; m++)
#pragma unroll
        for (int n = 0; n < TN; n++) acc[m][n] = 0.f;

    for (int k0 = 0; k0 < K; k0 += BK) {
        // Load A tile (BM x BK), store transposed into As
#pragma unroll
        for (int i = tid; i < BM * BK / 4; i += 256) {
            int r = (i * 4) / BK, c = (i * 4) % BK;
            float4 a = *(const float4*)(Ab + (size_t)r * K + k0 + c);
            As[c + 0][r] = a.x;
            As[c + 1][r] = a.y;
            As[c + 2][r] = a.z;
            As[c + 3][r] = a.w;
        }
        // Load B tile (BK x BN)
#pragma unroll
        for (int i = tid; i < BK * BN / 4; i += 256) {
            int r = (i * 4) / BN, c = (i * 4) % BN;
            *(float4*)&Bs[r][c] = *(const float4*)(Bb + (size_t)(k0 + r) * N + c);
        }
        __syncthreads();

#pragma unroll
        for (int k = 0; k < BK; k++) {
            float4 ra0 = *(const float4*)&As[k][tr * TM];
            float4 ra1 = *(const float4*)&As[k][tr * TM + 4];
            float4 rb0 = *(const float4*)&Bs[k][tc * TN];
            float4 rb1 = *(const float4*)&Bs[k][tc * TN + 4];
            float ra[TM] = {ra0.x, ra0.y, ra0.z, ra0.w, ra1.x, ra1.y, ra1.z, ra1.w};
            float rb[TN] = {rb0.x, rb0.y, rb0.z, rb0.w, rb1.x, rb1.y, rb1.z, rb1.w};
#pragma unroll
            for (int m = 0; m < TM; m++)
#pragma unroll
                for (int n = 0; n < TN; n++)
                    acc[m][n] += ra[m] * rb[n];
        }
        __syncthreads();
    }

    float* Cb = C + (size_t)blockIdx.y * BM * N + (size_t)blockIdx.x * BN;
#pragma unroll
    for (int m = 0; m < TM; m++) {
#pragma unroll
        for (int n = 0; n < TN; n += 4) {
            float4 v = make_float4(acc[m][n], acc[m][n + 1], acc[m][n + 2], acc[m][n + 3]);
            *(float4*)(Cb + (size_t)(tr * TM + m) * N + tc * TN + n) = v;
        }
    }
}

// ---------------------------------------------------------------------------
// Fused RMSNorm + RoPE on [B, S, nheads, D] buffer, in place.
// One block (128 threads) per (b, s, h) row.
// ---------------------------------------------------------------------------
__global__ void rmsnorm_rope_kernel(float* __restrict__ x,
                                    const float* __restrict__ w,
                                    const float* __restrict__ cosb,
                                    const float* __restrict__ sinb,
                                    int nheads) {
    const int idx = blockIdx.x;                 // (b*S + s)*nheads + h
    const int s   = (idx / nheads) % Sq;
    const int d   = threadIdx.x;                // 0..127
    float* row    = x + (size_t)idx * Dh;

    float v  = row[d];
    float ss = v * v;
#pragma unroll
    for (int off = 16; off > 0; off >>= 1)
        ss += __shfl_xor_sync(0xffffffffu, ss, off);

    __shared__ float red[4];
    if ((d & 31) == 0) red[d >> 5] = ss;
    __syncthreads();
    float tot  = red[0] + red[1] + red[2] + red[3];
    float rinv = rsqrtf(tot / Dh + 1e-6f);
    float xn   = v * rinv * w[d];

    __shared__ float sm[Dh];
    sm[d] = xn;
    __syncthreads();
    float rot = (d < Dh / 2) ? -sm[d + Dh / 2] : sm[d - Dh / 2];
    float c   = cosb[(size_t)s * Dh + d];
    float sn  = sinb[(size_t)s * Dh + d];
    row[d]    = xn * c + rot * sn;
}

// ---------------------------------------------------------------------------
// Flash attention (causal, fp32). One block per (b, h, q-tile of 64 rows).
// 256 threads = 16x16 grid; per thread: 4 q rows x 4 k cols (scores),
// 4 q rows x 8 d cols (output accumulator).
// ---------------------------------------------------------------------------
#define BQ   64
#define BKV  64
#define PADD 132   // row stride for 128-wide smem tiles
#define PPAD 68    // row stride for 64-wide P tile
#define FLASH_SMEM_BYTES (((BQ + 2 * BKV) * PADD + BQ * PPAD) * 4)

__global__ void __launch_bounds__(256, 1)
flash_kernel(const float* __restrict__ q,
             const float* __restrict__ k,
             const float* __restrict__ v,
             float* __restrict__ ctx) {
    extern __shared__ float fsm[];
    float* Qs = fsm;                       // [BQ][PADD]
    float* Ks = Qs + BQ * PADD;            // [BKV][PADD]
    float* Vs = Ks + BKV * PADD;           // [BKV][PADD]
    float* Ps = Vs + BKV * PADD;           // [BQ][PPAD]

    const int bh  = blockIdx.y;
    const int b   = bh / HQn;
    const int h   = bh % HQn;
    const int hkv = h / NREP;
    // Reverse order so the longest (largest q0) blocks start first.
    const int q0 = (gridDim.x - 1 - blockIdx.x) * BQ;

    const int tid = threadIdx.x;
    const int tr  = tid >> 4;    // 0..15 -> q rows tr*4..tr*4+3
    const int tc  = tid & 15;    // 0..15 -> k cols tc*4..tc*4+3, d cols tc*8..tc*8+7
    const float scale = 0.088388347648318447f;  // 1/sqrt(128)

    // Load Q tile
    const float* qbase = q + (((size_t)b * Sq + q0) * HQn + h) * Dh;
#pragma unroll
    for (int i = tid; i < BQ * Dh / 4; i += 256) {
        int r = (i * 4) / Dh, c = (i * 4) % Dh;
        *(float4*)&Qs[r * PADD + c] = *(const float4*)(qbase + (size_t)r * HQn * Dh + c);
    }

    float m[4], l[4], O[4][8];
#pragma unroll
    for (int i = 0; i < 4; i++) {
        m[i] = -1e30f;
        l[i] = 0.f;
#pragma unroll
        for (int j = 0; j < 8; j++) O[i][j] = 0.f;
    }

    const float* kbase = k + ((size_t)b * Sq * HKVn + hkv) * Dh;
    const float* vbase = v + ((size_t)b * Sq * HKVn + hkv) * Dh;

    const int kend = q0 + BQ;   // exclusive causal limit
    for (int k0 = 0; k0 < kend; k0 += BKV) {
        __syncthreads();
#pragma unroll
        for (int i = tid; i < BKV * Dh / 4; i += 256) {
            int r = (i * 4) / Dh, c = (i * 4) % Dh;
            *(float4*)&Ks[r * PADD + c] =
                *(const float4*)(kbase + (size_t)(k0 + r) * HKVn * Dh + c);
            *(float4*)&Vs[r * PADD + c] =
                *(const float4*)(vbase + (size_t)(k0 + r) * HKVn * Dh + c);
        }
        __syncthreads();

        // Scores: 4x4 per thread
        float sc[4][4];
#pragma unroll
        for (int i = 0; i < 4; i++)
#pragma unroll
            for (int j = 0; j < 4; j++) sc[i][j] = 0.f;

        for (int d = 0; d < Dh; d += 4) {
            float4 aq[4], bk[4];
#pragma unroll
            for (int i = 0; i < 4; i++)
                aq[i] = *(const float4*)&Qs[(tr * 4 + i) * PADD + d];
#pragma unroll
            for (int j = 0; j < 4; j++)
                bk[j] = *(const float4*)&Ks[(tc * 4 + j) * PADD + d];
#pragma unroll
            for (int i = 0; i < 4; i++)
#pragma unroll
                for (int j = 0; j < 4; j++) {
                    sc[i][j] += aq[i].x * bk[j].x;
                    sc[i][j] += aq[i].y * bk[j].y;
                    sc[i][j] += aq[i].z * bk[j].z;
                    sc[i][j] += aq[i].w * bk[j].w;
                }
        }

        const bool full = (k0 + BKV <= q0);
#pragma unroll
        for (int i = 0; i < 4; i++) {
            const int qg = q0 + tr * 4 + i;
#pragma unroll
            for (int j = 0; j < 4; j++) {
                const int kg = k0 + tc * 4 + j;
                sc[i][j] = (full || kg <= qg) ? sc[i][j] * scale : -1e30f;
            }
        }

        // Online softmax (row groups = 16 lanes sharing tr)
#pragma unroll
        for (int i = 0; i < 4; i++) {
            float tm = fmaxf(fmaxf(sc[i][0], sc[i][1]), fmaxf(sc[i][2], sc[i][3]));
#pragma unroll
            for (int off = 1; off < 16; off <<= 1)
                tm = fmaxf(tm, __shfl_xor_sync(0xffffffffu, tm, off, 16));
            const float mn   = fmaxf(m[i], tm);
            const float corr = __expf(m[i] - mn);
            float ps = 0.f;
#pragma unroll
            for (int j = 0; j < 4; j++) {
                sc[i][j] = __expf(sc[i][j] - mn);   // masked -> exp(-huge) = 0
                ps += sc[i][j];
            }
#pragma unroll
            for (int off = 1; off < 16; off <<= 1)
                ps += __shfl_xor_sync(0xffffffffu, ps, off, 16);
            l[i] = l[i] * corr + ps;
            m[i] = mn;
#pragma unroll
            for (int j = 0; j < 8; j++) O[i][j] *= corr;
#pragma unroll
            for (int j = 0; j < 4; j++)
                Ps[(tr * 4 + i) * PPAD + tc * 4 + j] = sc[i][j];
        }
        __syncthreads();

        // PV: O[i][j] += sum_kc P[row][kc] * V[kc][dcol]
        for (int kc = 0; kc < BKV; kc++) {
            float pv[4];
#pragma unroll
            for (int i = 0; i < 4; i++) pv[i] = Ps[(tr * 4 + i) * PPAD + kc];
            float4 v0 = *(const float4*)&Vs[kc * PADD + tc * 8];
            float4 v1 = *(const float4*)&Vs[kc * PADD + tc * 8 + 4];
            float vv[8] = {v0.x, v0.y, v0.z, v0.w, v1.x, v1.y, v1.z, v1.w};
#pragma unroll
            for (int i = 0; i < 4; i++)
#pragma unroll
                for (int j = 0; j < 8; j++)
                    O[i][j] += pv[i] * vv[j];
        }
    }

    // Normalize and write out
    float* cbase = ctx + (((size_t)b * Sq + q0) * HQn + h) * Dh;
#pragma unroll
    for (int i = 0; i < 4; i++) {
        const float inv = 1.f / l[i];
        float4 o0 = make_float4(O[i][0] * inv, O[i][1] * inv, O[i][2] * inv, O[i][3] * inv);
        float4 o1 = make_float4(O[i][4] * inv, O[i][5] * inv, O[i][6] * inv, O[i][7] * inv);
        float* dst = cbase + (size_t)(tr * 4 + i) * HQn * Dh + tc * 8;
        *(float4*)dst       = o0;
        *(float4*)(dst + 4) = o1;
    }
}

// ---------------------------------------------------------------------------
// Launch
// ---------------------------------------------------------------------------
extern "C" void kernel_launch(void* const* d_in, const int* in_sizes, int n_in,
                              void* d_out, int out_size) {
    const float* hidden = (const float*)d_in[0];
    const float* cosb   = (const float*)d_in[1];
    const float* sinb   = (const float*)d_in[2];
    // d_in[3] = attention_mask (pure causal; implemented directly)
    const float* Wq = (const float*)d_in[4];
    const float* Wk = (const float*)d_in[5];
    const float* Wv = (const float*)d_in[6];
    const float* Wo = (const float*)d_in[7];
    const float* qw = (const float*)d_in[8];
    const float* kw = (const float*)d_in[9];
    float* out = (float*)d_out;

    float *qb, *kb, *vb, *cb;
    cudaGetSymbolAddress((void**)&qb, g_q);
    cudaGetSymbolAddress((void**)&kb, g_k);
    cudaGetSymbolAddress((void**)&vb, g_v);
    cudaGetSymbolAddress((void**)&cb, g_ctx);

    const int M = Bq * Sq;  // 4096

    // QKV projections
    sgemm_kernel<128, 128, 16, 8, 8>
        <<<dim3(HQn * Dh / 128, M / 128), 256>>>(M, HQn * Dh, Hd, hidden, Wq, qb);
    sgemm_kernel<128, 128, 16, 8, 8>
        <<<dim3(HKVn * Dh / 128, M / 128), 256>>>(M, HKVn * Dh, Hd, hidden, Wk, kb);
    sgemm_kernel<128, 128, 16, 8, 8>
        <<<dim3(HKVn * Dh / 128, M / 128), 256>>>(M, HKVn * Dh, Hd, hidden, Wv, vb);

    // RMSNorm + RoPE
    rmsnorm_rope_kernel<<<Bq * Sq * HQn, Dh>>>(qb, qw, cosb, sinb, HQn);
    rmsnorm_rope_kernel<<<Bq * Sq * HKVn, Dh>>>(kb, kw, cosb, sinb, HKVn);

    // Flash attention
    cudaFuncSetAttribute(flash_kernel, cudaFuncAttributeMaxDynamicSharedMemorySize,
                         FLASH_SMEM_BYTES);
    flash_kernel<<<dim3(Sq / BQ, Bq * HQn), 256, FLASH_SMEM_BYTES>>>(qb, kb, vb, cb);

    // Output projection
    sgemm_kernel<128, 128, 16, 8, 8>
        <<<dim3(Hd / 128, M / 128), 256>>>(M, Hd, HQn * Dh, cb, Wo, out);
}

// round 3
// speedup vs baseline: 1.5309x; 1.5309x over previous
#include <cuda_runtime.h>
#include <cuda_bf16.h>
#include <cstdint>

// Problem constants (fixed by the dataset)
#define Bq   2
#define Sq   2048
#define Hd   2048
#define HQn  16
#define HKVn 4
#define Dh   128
#define NREP (HQn / HKVn)

// Scratch (device globals; no runtime allocation allowed)
__device__ float g_q[(size_t)Bq * Sq * HQn * Dh];    // 32 MB
__device__ float g_k[(size_t)Bq * Sq * HKVn * Dh];   // 8 MB
__device__ float g_v[(size_t)Bq * Sq * HKVn * Dh];   // 8 MB
__device__ float g_ctx[(size_t)Bq * Sq * HQn * Dh];  // 32 MB
__device__ float g_WqT[(size_t)2048 * 2048];         // 16 MB
__device__ float g_WkT[(size_t)512 * 2048];          // 4 MB
__device__ float g_WvT[(size_t)512 * 2048];          // 4 MB
__device__ float g_WoT[(size_t)2048 * 2048];         // 16 MB

__device__ __forceinline__ uint32_t f2tf32(float x) {
    uint32_t u;
    asm("cvt.rna.tf32.f32 %0, %1;" : "=r"(u) : "f"(x));
    return u;
}

__device__ __forceinline__ void mma_tf32(float* d, const uint32_t* a,
                                         const uint32_t* b) {
    asm volatile(
        "mma.sync.aligned.m16n8k8.row.col.f32.tf32.tf32.f32 "
        "{%0,%1,%2,%3}, {%4,%5,%6,%7}, {%8,%9}, {%0,%1,%2,%3};"
        : "+f"(d[0]), "+f"(d[1]), "+f"(d[2]), "+f"(d[3])
        : "r"(a[0]), "r"(a[1]), "r"(a[2]), "r"(a[3]), "r"(b[0]), "r"(b[1]));
}

// ---------------------------------------------------------------------------
// Weight transpose: out[C][R] = in[R][C]
// ---------------------------------------------------------------------------
__global__ void transpose_kernel(const float* __restrict__ in,
                                 float* __restrict__ out, int R, int C) {
    __shared__ float t[32][33];
    const int bx = blockIdx.x * 32, by = blockIdx.y * 32;
    const int x = threadIdx.x, y = threadIdx.y;
#pragma unroll
    for (int j = 0; j < 32; j += 8)
        t[y + j][x] = in[(size_t)(by + y + j) * C + bx + x];
    __syncthreads();
#pragma unroll
    for (int j = 0; j < 32; j += 8)
        out[(size_t)(bx + y + j) * R + by + x] = t[x][y + j];
}

// ---------------------------------------------------------------------------
// TF32 mma.sync GEMM.  C[M,N] = A[M,K] @ Bt[N,K]^T  (Bt = pre-transposed B).
// CTA tile 128x128, BK=16, 8 warps (2x4), warp tile 64x32.
// 2-stage smem double buffer, register prefetch, cvt to tf32 at STS time.
// blockIdx.z selects (B0,C0) vs (B1,C1) so K and V proj share one launch.
// ---------------------------------------------------------------------------
#define SA 20          // smem row stride in floats (conflict-free, 16B aligned)
#define GBK 16

__global__ void __launch_bounds__(256, 1)
gemm_tf32_mma(int M, int N, int K,
              const float* __restrict__ A,
              const float* __restrict__ B0, const float* __restrict__ B1,
              float* __restrict__ C0, float* __restrict__ C1) {
    __shared__ float As[2][128 * SA];
    __shared__ float Bs[2][128 * SA];

    const int tid  = threadIdx.x;
    const int lane = tid & 31, wid = tid >> 5;
    const int wm = (wid & 1) * 64;       // warp row offset in CTA tile
    const int wn = (wid >> 1) * 32;      // warp col offset
    const int g  = lane >> 2, tg = lane & 3;

    const float* Bt = blockIdx.z ? B1 : B0;
    float* C = blockIdx.z ? C1 : C0;
    const int m0 = blockIdx.y * 128, n0 = blockIdx.x * 128;
    const float* Ab = A + (size_t)m0 * K;
    const float* Bb = Bt + (size_t)n0 * K;

    // Per-thread global-load coords: 512 float4 per 128x16 tile, 2 per thread.
    const int r0 = tid >> 2;             // rows 0..63
    const int r1 = r0 + 64;              // rows 64..127
    const int c4 = (tid & 3) * 4;        // col 0,4,8,12

    float acc[4][4][4];
#pragma unroll
    for (int mi = 0; mi < 4; mi++)
#pragma unroll
        for (int ni = 0; ni < 4; ni++)
#pragma unroll
            for (int e = 0; e < 4; e++) acc[mi][ni][e] = 0.f;

    float4 pa0 = *(const float4*)(Ab + (size_t)r0 * K + c4);
    float4 pa1 = *(const float4*)(Ab + (size_t)r1 * K + c4);
    float4 pb0 = *(const float4*)(Bb + (size_t)r0 * K + c4);
    float4 pb1 = *(const float4*)(Bb + (size_t)r1 * K + c4);

    const int nk = K / GBK;
    for (int kt = 0; kt < nk; kt++) {
        const int st = kt & 1;
        float* as = As[st];
        float* bs = Bs[st];

        // cvt to tf32 and store
        {
            uint4 q;
            q.x = f2tf32(pa0.x); q.y = f2tf32(pa0.y);
            q.z = f2tf32(pa0.z); q.w = f2tf32(pa0.w);
            *(uint4*)&as[r0 * SA + c4] = q;
            q.x = f2tf32(pa1.x); q.y = f2tf32(pa1.y);
            q.z = f2tf32(pa1.z); q.w = f2tf32(pa1.w);
            *(uint4*)&as[r1 * SA + c4] = q;
            q.x = f2tf32(pb0.x); q.y = f2tf32(pb0.y);
            q.z = f2tf32(pb0.z); q.w = f2tf32(pb0.w);
            *(uint4*)&bs[r0 * SA + c4] = q;
            q.x = f2tf32(pb1.x); q.y = f2tf32(pb1.y);
            q.z = f2tf32(pb1.z); q.w = f2tf32(pb1.w);
            *(uint4*)&bs[r1 * SA + c4] = q;
        }
        __syncthreads();

        // Prefetch next chunk while computing this one
        if (kt + 1 < nk) {
            const int kk = (kt + 1) * GBK;
            pa0 = *(const float4*)(Ab + (size_t)r0 * K + kk + c4);
            pa1 = *(const float4*)(Ab + (size_t)r1 * K + kk + c4);
            pb0 = *(const float4*)(Bb + (size_t)r0 * K + kk + c4);
            pb1 = *(const float4*)(Bb + (size_t)r1 * K + kk + c4);
        }

#pragma unroll
        for (int ks = 0; ks < 2; ks++) {
            const int kb = ks * 8;
            uint32_t af[4][4], bf[4][2];
#pragma unroll
            for (int mi = 0; mi < 4; mi++) {
                const float* p = &as[(wm + mi * 16 + g) * SA + kb + tg];
                af[mi][0] = __float_as_uint(p[0]);
                af[mi][1] = __float_as_uint(p[8 * SA]);
                af[mi][2] = __float_as_uint(p[4]);
                af[mi][3] = __float_as_uint(p[8 * SA + 4]);
            }
#pragma unroll
            for (int ni = 0; ni < 4; ni++) {
                const float* p = &bs[(wn + ni * 8 + g) * SA + kb + tg];
                bf[ni][0] = __float_as_uint(p[0]);
                bf[ni][1] = __float_as_uint(p[4]);
            }
#pragma unroll
            for (int mi = 0; mi < 4; mi++)
#pragma unroll
                for (int ni = 0; ni < 4; ni++)
                    mma_tf32(acc[mi][ni], af[mi], bf[ni]);
        }
        // No trailing sync needed: next STS targets the other stage, and all
        // threads' compute on stage st^1 finished before the sync above.
    }

    // Epilogue
#pragma unroll
    for (int mi = 0; mi < 4; mi++) {
        const int row0 = m0 + wm + mi * 16 + g;
#pragma unroll
        for (int ni = 0; ni < 4; ni++) {
            const int col = n0 + wn + ni * 8 + tg * 2;
            float2 v0 = make_float2(acc[mi][ni][0], acc[mi][ni][1]);
            float2 v1 = make_float2(acc[mi][ni][2], acc[mi][ni][3]);
            *(float2*)&C[(size_t)row0 * N + col]       = v0;
            *(float2*)&C[(size_t)(row0 + 8) * N + col] = v1;
        }
    }
}

// ---------------------------------------------------------------------------
// Fused RMSNorm + RoPE on [B, S, nheads, D] buffer, in place.
// ---------------------------------------------------------------------------
__global__ void rmsnorm_rope_kernel(float* __restrict__ x,
                                    const float* __restrict__ w,
                                    const float* __restrict__ cosb,
                                    const float* __restrict__ sinb,
                                    int nheads) {
    const int idx = blockIdx.x;
    const int s   = (idx / nheads) % Sq;
    const int d   = threadIdx.x;
    float* row    = x + (size_t)idx * Dh;

    float v  = row[d];
    float ss = v * v;
#pragma unroll
    for (int off = 16; off > 0; off >>= 1)
        ss += __shfl_xor_sync(0xffffffffu, ss, off);

    __shared__ float red[4];
    if ((d & 31) == 0) red[d >> 5] = ss;
    __syncthreads();
    float tot  = red[0] + red[1] + red[2] + red[3];
    float rinv = rsqrtf(tot / Dh + 1e-6f);
    float xn   = v * rinv * w[d];

    __shared__ float sm[Dh];
    sm[d] = xn;
    __syncthreads();
    float rot = (d < Dh / 2) ? -sm[d + Dh / 2] : sm[d - Dh / 2];
    float c   = cosb[(size_t)s * Dh + d];
    float sn  = sinb[(size_t)s * Dh + d];
    row[d]    = xn * c + rot * sn;
}

// ---------------------------------------------------------------------------
// Flash attention (causal, fp32). Same as round 1.
// ---------------------------------------------------------------------------
#define BQ   64
#define BKV  64
#define PADD 132
#define PPAD 68
#define FLASH_SMEM_BYTES (((BQ + 2 * BKV) * PADD + BQ * PPAD) * 4)

__global__ void __launch_bounds__(256, 1)
flash_kernel(const float* __restrict__ q,
             const float* __restrict__ k,
             const float* __restrict__ v,
             float* __restrict__ ctx) {
    extern __shared__ float fsm[];
    float* Qs = fsm;
    float* Ks = Qs + BQ * PADD;
    float* Vs = Ks + BKV * PADD;
    float* Ps = Vs + BKV * PADD;

    const int bh  = blockIdx.y;
    const int b   = bh / HQn;
    const int h   = bh % HQn;
    const int hkv = h / NREP;
    const int q0 = (gridDim.x - 1 - blockIdx.x) * BQ;

    const int tid = threadIdx.x;
    const int tr  = tid >> 4;
    const int tc  = tid & 15;
    const float scale = 0.088388347648318447f;

    const float* qbase = q + (((size_t)b * Sq + q0) * HQn + h) * Dh;
#pragma unroll
    for (int i = tid; i < BQ * Dh / 4; i += 256) {
        int r = (i * 4) / Dh, c = (i * 4) % Dh;
        *(float4*)&Qs[r * PADD + c] = *(const float4*)(qbase + (size_t)r * HQn * Dh + c);
    }

    float m[4], l[4], O[4][8];
#pragma unroll
    for (int i = 0; i < 4; i++) {
        m[i] = -1e30f;
        l[i] = 0.f;
#pragma unroll
        for (int j = 0; j < 8; j++) O[i][j] = 0.f;
    }

    const float* kbase = k + ((size_t)b * Sq * HKVn + hkv) * Dh;
    const float* vbase = v + ((size_t)b * Sq * HKVn + hkv) * Dh;

    const int kend = q0 + BQ;
    for (int k0 = 0; k0 < kend; k0 += BKV) {
        __syncthreads();
#pragma unroll
        for (int i = tid; i < BKV * Dh / 4; i += 256) {
            int r = (i * 4) / Dh, c = (i * 4) % Dh;
            *(float4*)&Ks[r * PADD + c] =
                *(const float4*)(kbase + (size_t)(k0 + r) * HKVn * Dh + c);
            *(float4*)&Vs[r * PADD + c] =
                *(const float4*)(vbase + (size_t)(k0 + r) * HKVn * Dh + c);
        }
        __syncthreads();

        float sc[4][4];
#pragma unroll
        for (int i = 0; i < 4; i++)
#pragma unroll
            for (int j = 0; j < 4; j++) sc[i][j] = 0.f;

        for (int d = 0; d < Dh; d += 4) {
            float4 aq[4], bk[4];
#pragma unroll
            for (int i = 0; i < 4; i++)
                aq[i] = *(const float4*)&Qs[(tr * 4 + i) * PADD + d];
#pragma unroll
            for (int j = 0; j < 4; j++)
                bk[j] = *(const float4*)&Ks[(tc * 4 + j) * PADD + d];
#pragma unroll
            for (int i = 0; i < 4; i++)
#pragma unroll
                for (int j = 0; j < 4; j++) {
                    sc[i][j] += aq[i].x * bk[j].x;
                    sc[i][j] += aq[i].y * bk[j].y;
                    sc[i][j] += aq[i].z * bk[j].z;
                    sc[i][j] += aq[i].w * bk[j].w;
                }
        }

        const bool full = (k0 + BKV <= q0);
#pragma unroll
        for (int i = 0; i < 4; i++) {
            const int qg = q0 + tr * 4 + i;
#pragma unroll
            for (int j = 0; j < 4; j++) {
                const int kg = k0 + tc * 4 + j;
                sc[i][j] = (full || kg <= qg) ? sc[i][j] * scale : -1e30f;
            }
        }

#pragma unroll
        for (int i = 0; i < 4; i++) {
            float tm = fmaxf(fmaxf(sc[i][0], sc[i][1]), fmaxf(sc[i][2], sc[i][3]));
#pragma unroll
            for (int off = 1; off < 16; off <<= 1)
                tm = fmaxf(tm, __shfl_xor_sync(0xffffffffu, tm, off, 16));
            const float mn   = fmaxf(m[i], tm);
            const float corr = __expf(m[i] - mn);
            float ps = 0.f;
#pragma unroll
            for (int j = 0; j < 4; j++) {
                sc[i][j] = __expf(sc[i][j] - mn);
                ps += sc[i][j];
            }
#pragma unroll
            for (int off = 1; off < 16; off <<= 1)
                ps += __shfl_xor_sync(0xffffffffu, ps, off, 16);
            l[i] = l[i] * corr + ps;
            m[i] = mn;
#pragma unroll
            for (int j = 0; j < 8; j++) O[i][j] *= corr;
#pragma unroll
            for (int j = 0; j < 4; j++)
                Ps[(tr * 4 + i) * PPAD + tc * 4 + j] = sc[i][j];
        }
        __syncthreads();

        for (int kc = 0; kc < BKV; kc++) {
            float pv[4];
#pragma unroll
            for (int i = 0; i < 4; i++) pv[i] = Ps[(tr * 4 + i) * PPAD + kc];
            float4 v0 = *(const float4*)&Vs[kc * PADD + tc * 8];
            float4 v1 = *(const float4*)&Vs[kc * PADD + tc * 8 + 4];
            float vv[8] = {v0.x, v0.y, v0.z, v0.w, v1.x, v1.y, v1.z, v1.w};
#pragma unroll
            for (int i = 0; i < 4; i++)
#pragma unroll
                for (int j = 0; j < 8; j++)
                    O[i][j] += pv[i] * vv[j];
        }
    }

    float* cbase = ctx + (((size_t)b * Sq + q0) * HQn + h) * Dh;
#pragma unroll
    for (int i = 0; i < 4; i++) {
        const float inv = 1.f / l[i];
        float4 o0 = make_float4(O[i][0] * inv, O[i][1] * inv, O[i][2] * inv, O[i][3] * inv);
        float4 o1 = make_float4(O[i][4] * inv, O[i][5] * inv, O[i][6] * inv, O[i][7] * inv);
        float* dst = cbase + (size_t)(tr * 4 + i) * HQn * Dh + tc * 8;
        *(float4*)dst       = o0;
        *(float4*)(dst + 4) = o1;
    }
}

// ---------------------------------------------------------------------------
// Launch
// ---------------------------------------------------------------------------
extern "C" void kernel_launch(void* const* d_in, const int* in_sizes, int n_in,
                              void* d_out, int out_size) {
    const float* hidden = (const float*)d_in[0];
    const float* cosb   = (const float*)d_in[1];
    const float* sinb   = (const float*)d_in[2];
    const float* Wq = (const float*)d_in[4];
    const float* Wk = (const float*)d_in[5];
    const float* Wv = (const float*)d_in[6];
    const float* Wo = (const float*)d_in[7];
    const float* qw = (const float*)d_in[8];
    const float* kw = (const float*)d_in[9];
    float* out = (float*)d_out;

    float *qb, *kb, *vb, *cb, *wqT, *wkT, *wvT, *woT;
    cudaGetSymbolAddress((void**)&qb, g_q);
    cudaGetSymbolAddress((void**)&kb, g_k);
    cudaGetSymbolAddress((void**)&vb, g_v);
    cudaGetSymbolAddress((void**)&cb, g_ctx);
    cudaGetSymbolAddress((void**)&wqT, g_WqT);
    cudaGetSymbolAddress((void**)&wkT, g_WkT);
    cudaGetSymbolAddress((void**)&wvT, g_WvT);
    cudaGetSymbolAddress((void**)&woT, g_WoT);

    const int M = Bq * Sq;  // 4096

    // Weight transposes (B operands must be K-major)
    transpose_kernel<<<dim3(2048 / 32, 2048 / 32), dim3(32, 8)>>>(Wq, wqT, 2048, 2048);
    transpose_kernel<<<dim3(512 / 32, 2048 / 32), dim3(32, 8)>>>(Wk, wkT, 2048, 512);
    transpose_kernel<<<dim3(512 / 32, 2048 / 32), dim3(32, 8)>>>(Wv, wvT, 2048, 512);
    transpose_kernel<<<dim3(2048 / 32, 2048 / 32), dim3(32, 8)>>>(Wo, woT, 2048, 2048);

    // Q projection
    gemm_tf32_mma<<<dim3(2048 / 128, M / 128, 1), 256>>>(
        M, 2048, 2048, hidden, wqT, wqT, qb, qb);
    // K and V projections in one launch (blockIdx.z)
    gemm_tf32_mma<<<dim3(512 / 128, M / 128, 2), 256>>>(
        M, 512, 2048, hidden, wkT, wvT, kb, vb);

    // RMSNorm + RoPE
    rmsnorm_rope_kernel<<<Bq * Sq * HQn, Dh>>>(qb, qw, cosb, sinb, HQn);
    rmsnorm_rope_kernel<<<Bq * Sq * HKVn, Dh>>>(kb, kw, cosb, sinb, HKVn);

    // Flash attention
    cudaFuncSetAttribute(flash_kernel, cudaFuncAttributeMaxDynamicSharedMemorySize,
                         FLASH_SMEM_BYTES);
    flash_kernel<<<dim3(Sq / BQ, Bq * HQn), 256, FLASH_SMEM_BYTES>>>(qb, kb, vb, cb);

    // Output projection
    gemm_tf32_mma<<<dim3(2048 / 128, M / 128, 1), 256>>>(
        M, 2048, 2048, cb, woT, woT, out, out);
}

// round 4
// speedup vs baseline: 2.7555x; 1.7999x over previous
#include <cuda_runtime.h>
#include <cuda_bf16.h>
#include <cstdint>

// Problem constants (fixed by the dataset)
#define Bq   2
#define Sq   2048
#define Hd   2048
#define HQn  16
#define HKVn 4
#define Dh   128
#define NREP (HQn / HKVn)

// Scratch (device globals; no runtime allocation allowed)
__device__ float g_q[(size_t)Bq * Sq * HQn * Dh];    // 32 MB
__device__ float g_k[(size_t)Bq * Sq * HKVn * Dh];   // 8 MB
__device__ float g_v[(size_t)Bq * Sq * HKVn * Dh];   // 8 MB
__device__ float g_ctx[(size_t)Bq * Sq * HQn * Dh];  // 32 MB
__device__ float g_WqT[(size_t)2048 * 2048];         // 16 MB
__device__ float g_WkT[(size_t)512 * 2048];          // 4 MB
__device__ float g_WvT[(size_t)512 * 2048];          // 4 MB
__device__ float g_WoT[(size_t)2048 * 2048];         // 16 MB

__device__ __forceinline__ uint32_t f2tf32(float x) {
    uint32_t u;
    asm("cvt.rna.tf32.f32 %0, %1;" : "=r"(u) : "f"(x));
    return u;
}

__device__ __forceinline__ void mma_tf32(float* d, const uint32_t* a,
                                         const uint32_t* b) {
    asm volatile(
        "mma.sync.aligned.m16n8k8.row.col.f32.tf32.tf32.f32 "
        "{%0,%1,%2,%3}, {%4,%5,%6,%7}, {%8,%9}, {%0,%1,%2,%3};"
        : "+f"(d[0]), "+f"(d[1]), "+f"(d[2]), "+f"(d[3])
        : "r"(a[0]), "r"(a[1]), "r"(a[2]), "r"(a[3]), "r"(b[0]), "r"(b[1]));
}

// exp(x) for x <= 0 via FFMA-pipe exp2 polynomial (degree 6, rel err <1e-5).
// Avoids the MUFU bottleneck (rt=8/SMSP).
__device__ __forceinline__ float fexp(float x) {
    float t  = fmaxf(x, -87.0f) * 1.4426950408889634f;   // log2(e)
    float fl = floorf(t);
    float f  = t - fl;
    float p  = 1.5403531e-4f;
    p = fmaf(p, f, 1.3333558e-3f);
    p = fmaf(p, f, 9.6181291e-3f);
    p = fmaf(p, f, 5.5504108e-2f);
    p = fmaf(p, f, 2.4022650e-1f);
    p = fmaf(p, f, 6.9314718e-1f);
    p = fmaf(p, f, 1.0f);
    int e = (int)fl;
    return __int_as_float((uint32_t)(e + 127) << 23) * p;
}

// ---------------------------------------------------------------------------
// Weight transpose: out[C][R] = in[R][C]
// ---------------------------------------------------------------------------
__global__ void transpose_kernel(const float* __restrict__ in,
                                 float* __restrict__ out, int R, int C) {
    __shared__ float t[32][33];
    const int bx = blockIdx.x * 32, by = blockIdx.y * 32;
    const int x = threadIdx.x, y = threadIdx.y;
#pragma unroll
    for (int j = 0; j < 32; j += 8)
        t[y + j][x] = in[(size_t)(by + y + j) * C + bx + x];
    __syncthreads();
#pragma unroll
    for (int j = 0; j < 32; j += 8)
        out[(size_t)(bx + y + j) * R + by + x] = t[x][y + j];
}

// ---------------------------------------------------------------------------
// TF32 mma.sync GEMM (unchanged from round 3, passing).
// ---------------------------------------------------------------------------
#define SA 20
#define GBK 16

__global__ void __launch_bounds__(256, 1)
gemm_tf32_mma(int M, int N, int K,
              const float* __restrict__ A,
              const float* __restrict__ B0, const float* __restrict__ B1,
              float* __restrict__ C0, float* __restrict__ C1) {
    __shared__ float As[2][128 * SA];
    __shared__ float Bs[2][128 * SA];

    const int tid  = threadIdx.x;
    const int lane = tid & 31, wid = tid >> 5;
    const int wm = (wid & 1) * 64;
    const int wn = (wid >> 1) * 32;
    const int g  = lane >> 2, tg = lane & 3;

    const float* Bt = blockIdx.z ? B1 : B0;
    float* C = blockIdx.z ? C1 : C0;
    const int m0 = blockIdx.y * 128, n0 = blockIdx.x * 128;
    const float* Ab = A + (size_t)m0 * K;
    const float* Bb = Bt + (size_t)n0 * K;

    const int r0 = tid >> 2;
    const int r1 = r0 + 64;
    const int c4 = (tid & 3) * 4;

    float acc[4][4][4];
#pragma unroll
    for (int mi = 0; mi < 4; mi++)
#pragma unroll
        for (int ni = 0; ni < 4; ni++)
#pragma unroll
            for (int e = 0; e < 4; e++) acc[mi][ni][e] = 0.f;

    float4 pa0 = *(const float4*)(Ab + (size_t)r0 * K + c4);
    float4 pa1 = *(const float4*)(Ab + (size_t)r1 * K + c4);
    float4 pb0 = *(const float4*)(Bb + (size_t)r0 * K + c4);
    float4 pb1 = *(const float4*)(Bb + (size_t)r1 * K + c4);

    const int nk = K / GBK;
    for (int kt = 0; kt < nk; kt++) {
        const int st = kt & 1;
        float* as = As[st];
        float* bs = Bs[st];
        {
            uint4 q;
            q.x = f2tf32(pa0.x); q.y = f2tf32(pa0.y);
            q.z = f2tf32(pa0.z); q.w = f2tf32(pa0.w);
            *(uint4*)&as[r0 * SA + c4] = q;
            q.x = f2tf32(pa1.x); q.y = f2tf32(pa1.y);
            q.z = f2tf32(pa1.z); q.w = f2tf32(pa1.w);
            *(uint4*)&as[r1 * SA + c4] = q;
            q.x = f2tf32(pb0.x); q.y = f2tf32(pb0.y);
            q.z = f2tf32(pb0.z); q.w = f2tf32(pb0.w);
            *(uint4*)&bs[r0 * SA + c4] = q;
            q.x = f2tf32(pb1.x); q.y = f2tf32(pb1.y);
            q.z = f2tf32(pb1.z); q.w = f2tf32(pb1.w);
            *(uint4*)&bs[r1 * SA + c4] = q;
        }
        __syncthreads();

        if (kt + 1 < nk) {
            const int kk = (kt + 1) * GBK;
            pa0 = *(const float4*)(Ab + (size_t)r0 * K + kk + c4);
            pa1 = *(const float4*)(Ab + (size_t)r1 * K + kk + c4);
            pb0 = *(const float4*)(Bb + (size_t)r0 * K + kk + c4);
            pb1 = *(const float4*)(Bb + (size_t)r1 * K + kk + c4);
        }

#pragma unroll
        for (int ks = 0; ks < 2; ks++) {
            const int kb = ks * 8;
            uint32_t af[4][4], bf[4][2];
#pragma unroll
            for (int mi = 0; mi < 4; mi++) {
                const float* p = &as[(wm + mi * 16 + g) * SA + kb + tg];
                af[mi][0] = __float_as_uint(p[0]);
                af[mi][1] = __float_as_uint(p[8 * SA]);
                af[mi][2] = __float_as_uint(p[4]);
                af[mi][3] = __float_as_uint(p[8 * SA + 4]);
            }
#pragma unroll
            for (int ni = 0; ni < 4; ni++) {
                const float* p = &bs[(wn + ni * 8 + g) * SA + kb + tg];
                bf[ni][0] = __float_as_uint(p[0]);
                bf[ni][1] = __float_as_uint(p[4]);
            }
#pragma unroll
            for (int mi = 0; mi < 4; mi++)
#pragma unroll
                for (int ni = 0; ni < 4; ni++)
                    mma_tf32(acc[mi][ni], af[mi], bf[ni]);
        }
    }

#pragma unroll
    for (int mi = 0; mi < 4; mi++) {
        const int row0 = m0 + wm + mi * 16 + g;
#pragma unroll
        for (int ni = 0; ni < 4; ni++) {
            const int col = n0 + wn + ni * 8 + tg * 2;
            float2 v0 = make_float2(acc[mi][ni][0], acc[mi][ni][1]);
            float2 v1 = make_float2(acc[mi][ni][2], acc[mi][ni][3]);
            *(float2*)&C[(size_t)row0 * N + col]       = v0;
            *(float2*)&C[(size_t)(row0 + 8) * N + col] = v1;
        }
    }
}

// ---------------------------------------------------------------------------
// Fused RMSNorm + RoPE (unchanged).
// ---------------------------------------------------------------------------
__global__ void rmsnorm_rope_kernel(float* __restrict__ x,
                                    const float* __restrict__ w,
                                    const float* __restrict__ cosb,
                                    const float* __restrict__ sinb,
                                    int nheads) {
    const int idx = blockIdx.x;
    const int s   = (idx / nheads) % Sq;
    const int d   = threadIdx.x;
    float* row    = x + (size_t)idx * Dh;

    float v  = row[d];
    float ss = v * v;
#pragma unroll
    for (int off = 16; off > 0; off >>= 1)
        ss += __shfl_xor_sync(0xffffffffu, ss, off);

    __shared__ float red[4];
    if ((d & 31) == 0) red[d >> 5] = ss;
    __syncthreads();
    float tot  = red[0] + red[1] + red[2] + red[3];
    float rinv = rsqrtf(tot / Dh + 1e-6f);
    float xn   = v * rinv * w[d];

    __shared__ float sm[Dh];
    sm[d] = xn;
    __syncthreads();
    float rot = (d < Dh / 2) ? -sm[d + Dh / 2] : sm[d - Dh / 2];
    float c   = cosb[(size_t)s * Dh + d];
    float sn  = sinb[(size_t)s * Dh + d];
    row[d]    = xn * c + rot * sn;
}

// ---------------------------------------------------------------------------
// Flash attention via tf32 mma.sync. BQ=128 (8 warps x 16 rows), BKV=64.
// QK^T: Q single tf32 (scale folded in), K hi/lo split (2 MMAs).
// PV:   P single tf32, V^T hi/lo split (2 MMAs).
// exp via FFMA polynomial. P smem aliases the K region (freed after scores).
// ---------------------------------------------------------------------------
#define FBQ  128
#define FBKV 64
#define QS_S 132
#define KS_S 132
#define VS_S 68
#define PS_S 68
#define OFF_Q   0
#define OFF_KHI (FBQ * QS_S)                 // 16896
#define OFF_KLO (OFF_KHI + FBKV * KS_S)      // 25344
#define OFF_VHI (OFF_KLO + FBKV * KS_S)      // 33792
#define OFF_VLO (OFF_VHI + Dh * VS_S)        // 42496
#define OFF_P   OFF_KHI                      // alias: K dead after score phase
#define FLASH_SMEM_BYTES ((OFF_VLO + Dh * VS_S) * 4)   // 204800

__global__ void __launch_bounds__(256, 1)
flash_mma_kernel(const float* __restrict__ q,
                 const float* __restrict__ k,
                 const float* __restrict__ v,
                 float* __restrict__ ctx) {
    extern __shared__ float fs[];
    uint32_t* fsu = (uint32_t*)fs;

    const int bh  = blockIdx.y;
    const int b   = bh / HQn;
    const int h   = bh % HQn;
    const int hkv = h / NREP;
    const int q0  = (gridDim.x - 1 - blockIdx.x) * FBQ;  // longest work first

    const int tid  = threadIdx.x;
    const int lane = tid & 31, wid = tid >> 5;
    const int g = lane >> 2, tg = lane & 3;
    const int wband = wid * 16;
    const float scale = 0.088388347648318447f;  // 1/sqrt(128)

    // Load Q tile (scale folded in, tf32 single). Coalesced rows.
    const float* qbase = q + (((size_t)b * Sq + q0) * HQn + h) * Dh;
#pragma unroll
    for (int i = tid; i < FBQ * Dh / 4; i += 256) {
        const int r = i >> 5, c = (i & 31) * 4;
        float4 x = *(const float4*)(qbase + (size_t)r * HQn * Dh + c);
        uint4 t;
        t.x = f2tf32(x.x * scale); t.y = f2tf32(x.y * scale);
        t.z = f2tf32(x.z * scale); t.w = f2tf32(x.w * scale);
        *(uint4*)&fsu[OFF_Q + r * QS_S + c] = t;
    }

    float m[2], l[2], O[16][4];
    m[0] = m[1] = -1e30f;
    l[0] = l[1] = 0.f;
#pragma unroll
    for (int nt = 0; nt < 16; nt++)
#pragma unroll
        for (int e = 0; e < 4; e++) O[nt][e] = 0.f;

    const float* kbase = k + ((size_t)b * Sq * HKVn + hkv) * Dh;
    const float* vbase = v + ((size_t)b * Sq * HKVn + hkv) * Dh;

    const int kend = q0 + FBQ;
    for (int k0 = 0; k0 < kend; k0 += FBKV) {
        // Sync: previous PV (reads P in K-region + Vt) done before overwrite.
        __syncthreads();

        // K tile: coalesced load, hi/lo split store.
#pragma unroll
        for (int i = tid; i < FBKV * Dh / 4; i += 256) {
            const int r = i >> 5, c = (i & 31) * 4;
            float4 x = *(const float4*)(kbase + (size_t)(k0 + r) * HKVn * Dh + c);
            uint4 hi, lo;
            hi.x = f2tf32(x.x); lo.x = f2tf32(x.x - __uint_as_float(hi.x));
            hi.y = f2tf32(x.y); lo.y = f2tf32(x.y - __uint_as_float(hi.y));
            hi.z = f2tf32(x.z); lo.z = f2tf32(x.z - __uint_as_float(hi.z));
            hi.w = f2tf32(x.w); lo.w = f2tf32(x.w - __uint_as_float(hi.w));
            *(uint4*)&fsu[OFF_KHI + r * KS_S + c] = hi;
            *(uint4*)&fsu[OFF_KLO + r * KS_S + c] = lo;
        }
        // V tile: row-per-lane load (conflict-free transpose store into Vt).
#pragma unroll
        for (int i = tid; i < FBKV * Dh / 4; i += 256) {
            const int r = i & 63, c = (i >> 6) * 4;
            float4 x = *(const float4*)(vbase + (size_t)(k0 + r) * HKVn * Dh + c);
#pragma unroll
            for (int j = 0; j < 4; j++) {
                const float val = (&x.x)[j];
                const uint32_t hi = f2tf32(val);
                fsu[OFF_VHI + (c + j) * VS_S + r] = hi;
                fsu[OFF_VLO + (c + j) * VS_S + r] =
                    f2tf32(val - __uint_as_float(hi));
            }
        }
        __syncthreads();

        // ---- Scores: warp computes its 16 rows x 64 kv ----
        float sc[8][4];
#pragma unroll
        for (int nt = 0; nt < 8; nt++)
#pragma unroll
            for (int e = 0; e < 4; e++) sc[nt][e] = 0.f;

#pragma unroll
        for (int ks = 0; ks < 16; ks++) {
            const int kb = ks * 8;
            uint32_t a[4];
            {
                const uint32_t* p = &fsu[OFF_Q + (wband + g) * QS_S + kb + tg];
                a[0] = p[0];
                a[1] = p[8 * QS_S];
                a[2] = p[4];
                a[3] = p[8 * QS_S + 4];
            }
#pragma unroll
            for (int nt = 0; nt < 8; nt++) {
                const uint32_t* ph = &fsu[OFF_KHI + (nt * 8 + g) * KS_S + kb + tg];
                const uint32_t* pl = &fsu[OFF_KLO + (nt * 8 + g) * KS_S + kb + tg];
                uint32_t bh_[2] = {ph[0], ph[4]};
                uint32_t bl_[2] = {pl[0], pl[4]};
                mma_tf32(sc[nt], a, bh_);
                mma_tf32(sc[nt], a, bl_);
            }
        }

        // Causal mask (only the last two tiles of each CTA intersect the diag).
        if (k0 + FBKV > q0 + 1 - 1) {       // k0 + 63 > q0  -> partial tile
            if (k0 + FBKV - 1 > q0) {
#pragma unroll
                for (int nt = 0; nt < 8; nt++)
#pragma unroll
                    for (int e = 0; e < 4; e++) {
                        const int qg = q0 + wband + g + ((e >> 1) << 3);
                        const int kg = k0 + nt * 8 + tg * 2 + (e & 1);
                        if (kg > qg) sc[nt][e] = -1e30f;
                    }
            }
        }

        // Sync: all warps done reading K before P overwrites the K region.
        __syncthreads();

        // ---- Online softmax (rows g and g+8; 4 lanes share each row) ----
        float corr[2], ps[2];
#pragma unroll
        for (int r2 = 0; r2 < 2; r2++) {
            float tm = -1e30f;
#pragma unroll
            for (int nt = 0; nt < 8; nt++)
                tm = fmaxf(tm, fmaxf(sc[nt][r2 * 2], sc[nt][r2 * 2 + 1]));
            tm = fmaxf(tm, __shfl_xor_sync(0xffffffffu, tm, 1));
            tm = fmaxf(tm, __shfl_xor_sync(0xffffffffu, tm, 2));
            const float mn = fmaxf(m[r2], tm);
            corr[r2] = fexp(m[r2] - mn);
            m[r2] = mn;
            float s2 = 0.f;
            const int prow = (wband + g + r2 * 8) * PS_S;
#pragma unroll
            for (int nt = 0; nt < 8; nt++) {
                float p0 = fexp(sc[nt][r2 * 2]     - mn);
                float p1 = fexp(sc[nt][r2 * 2 + 1] - mn);
                uint32_t t0 = f2tf32(p0), t1 = f2tf32(p1);
                s2 += __uint_as_float(t0) + __uint_as_float(t1);
                *(uint2*)&fsu[OFF_P + prow + nt * 8 + tg * 2] =
                    make_uint2(t0, t1);
            }
            s2 += __shfl_xor_sync(0xffffffffu, s2, 1);
            s2 += __shfl_xor_sync(0xffffffffu, s2, 2);
            ps[r2] = s2;
            l[r2] = l[r2] * corr[r2] + s2;
        }
        (void)ps;

        // Rescale O
#pragma unroll
        for (int nt = 0; nt < 16; nt++) {
            O[nt][0] *= corr[0]; O[nt][1] *= corr[0];
            O[nt][2] *= corr[1]; O[nt][3] *= corr[1];
        }
        __syncwarp();

        // ---- PV: O += P @ V  (P own-warp rows; Vt shared, hi/lo split) ----
#pragma unroll
        for (int ks = 0; ks < 8; ks++) {
            const int kb = ks * 8;
            uint32_t a[4];
            {
                const uint32_t* p = &fsu[OFF_P + (wband + g) * PS_S + kb + tg];
                a[0] = p[0];
                a[1] = p[8 * PS_S];
                a[2] = p[4];
                a[3] = p[8 * PS_S + 4];
            }
#pragma unroll
            for (int nt = 0; nt < 16; nt++) {
                const uint32_t* ph = &fsu[OFF_VHI + (nt * 8 + g) * VS_S + kb + tg];
                const uint32_t* pl = &fsu[OFF_VLO + (nt * 8 + g) * VS_S + kb + tg];
                uint32_t bh_[2] = {ph[0], ph[4]};
                uint32_t bl_[2] = {pl[0], pl[4]};
                mma_tf32(O[nt], a, bh_);
                mma_tf32(O[nt], a, bl_);
            }
        }
    }

    // ---- Write output ----
    const float inv0 = 1.f / l[0];
    const float inv1 = 1.f / l[1];
    const int row0 = q0 + wband + g;
    float* base0 = ctx + (((size_t)b * Sq + row0) * HQn + h) * Dh;
    float* base1 = base0 + (size_t)8 * HQn * Dh;
#pragma unroll
    for (int nt = 0; nt < 16; nt++) {
        const int col = nt * 8 + tg * 2;
        *(float2*)&base0[col] = make_float2(O[nt][0] * inv0, O[nt][1] * inv0);
        *(float2*)&base1[col] = make_float2(O[nt][2] * inv1, O[nt][3] * inv1);
    }
}

// ---------------------------------------------------------------------------
// Launch
// ---------------------------------------------------------------------------
extern "C" void kernel_launch(void* const* d_in, const int* in_sizes, int n_in,
                              void* d_out, int out_size) {
    const float* hidden = (const float*)d_in[0];
    const float* cosb   = (const float*)d_in[1];
    const float* sinb   = (const float*)d_in[2];
    const float* Wq = (const float*)d_in[4];
    const float* Wk = (const float*)d_in[5];
    const float* Wv = (const float*)d_in[6];
    const float* Wo = (const float*)d_in[7];
    const float* qw = (const float*)d_in[8];
    const float* kw = (const float*)d_in[9];
    float* out = (float*)d_out;

    float *qb, *kb, *vb, *cb, *wqT, *wkT, *wvT, *woT;
    cudaGetSymbolAddress((void**)&qb, g_q);
    cudaGetSymbolAddress((void**)&kb, g_k);
    cudaGetSymbolAddress((void**)&vb, g_v);
    cudaGetSymbolAddress((void**)&cb, g_ctx);
    cudaGetSymbolAddress((void**)&wqT, g_WqT);
    cudaGetSymbolAddress((void**)&wkT, g_WkT);
    cudaGetSymbolAddress((void**)&wvT, g_WvT);
    cudaGetSymbolAddress((void**)&woT, g_WoT);

    const int M = Bq * Sq;  // 4096

    // Weight transposes (B operands must be K-major)
    transpose_kernel<<<dim3(2048 / 32, 2048 / 32), dim3(32, 8)>>>(Wq, wqT, 2048, 2048);
    transpose_kernel<<<dim3(512 / 32, 2048 / 32), dim3(32, 8)>>>(Wk, wkT, 2048, 512);
    transpose_kernel<<<dim3(512 / 32, 2048 / 32), dim3(32, 8)>>>(Wv, wvT, 2048, 512);
    transpose_kernel<<<dim3(2048 / 32, 2048 / 32), dim3(32, 8)>>>(Wo, woT, 2048, 2048);

    // Q projection
    gemm_tf32_mma<<<dim3(2048 / 128, M / 128, 1), 256>>>(
        M, 2048, 2048, hidden, wqT, wqT, qb, qb);
    // K and V projections in one launch (blockIdx.z)
    gemm_tf32_mma<<<dim3(512 / 128, M / 128, 2), 256>>>(
        M, 512, 2048, hidden, wkT, wvT, kb, vb);

    // RMSNorm + RoPE
    rmsnorm_rope_kernel<<<Bq * Sq * HQn, Dh>>>(qb, qw, cosb, sinb, HQn);
    rmsnorm_rope_kernel<<<Bq * Sq * HKVn, Dh>>>(kb, kw, cosb, sinb, HKVn);

    // Flash attention (tf32 mma)
    cudaFuncSetAttribute(flash_mma_kernel,
                         cudaFuncAttributeMaxDynamicSharedMemorySize,
                         FLASH_SMEM_BYTES);
    flash_mma_kernel<<<dim3(Sq / FBQ, Bq * HQn), 256, FLASH_SMEM_BYTES>>>(
        qb, kb, vb, cb);

    // Output projection
    gemm_tf32_mma<<<dim3(2048 / 128, M / 128, 1), 256>>>(
        M, 2048, 2048, cb, woT, woT, out, out);
}

// round 5
// speedup vs baseline: 3.6908x; 1.3394x over previous
#include <cuda_runtime.h>
#include <cstdint>

// Problem constants (fixed by the dataset)
#define Bq   2
#define Sq   2048
#define Hd   2048
#define HQn  16
#define HKVn 4
#define Dh   128
#define NREP (HQn / HKVn)

// Scratch (device globals; no runtime allocation allowed)
__device__ float g_q[(size_t)Bq * Sq * HQn * Dh];     // 32 MB
__device__ float g_k[(size_t)Bq * Sq * HKVn * Dh];    // 8 MB
__device__ float g_v[(size_t)Bq * Sq * HKVn * Dh];    // 8 MB
__device__ float g_ctx[(size_t)Bq * Sq * HQn * Dh];   // 32 MB
__device__ float g_hidR[(size_t)Bq * Sq * Hd];        // 32 MB (rounded hidden)
__device__ float g_WqkvT[(size_t)3072 * 2048];        // 24 MB (rounded, transposed)
__device__ float g_WoT[(size_t)2048 * 2048];          // 16 MB (rounded, transposed)
__device__ float g_vThi[(size_t)Bq * HKVn * Dh * Sq]; // 8 MB (V^T hi, rounded)
__device__ float g_vTlo[(size_t)Bq * HKVn * Dh * Sq]; // 8 MB (V^T lo, rounded)

// ---------------------------------------------------------------------------
// Helpers
// ---------------------------------------------------------------------------
__device__ __forceinline__ uint32_t smem_to_u32(const void* p) {
    uint32_t a;
    asm("{ .reg .u64 t; cvta.to.shared.u64 t, %1; cvt.u32.u64 %0, t; }"
        : "=r"(a) : "l"(p));
    return a;
}

__device__ __forceinline__ uint32_t f2tf32(float x) {
    uint32_t u;
    asm("cvt.rna.tf32.f32 %0, %1;" : "=r"(u) : "f"(x));
    return u;
}
__device__ __forceinline__ float roundtf(float x) {
    return __uint_as_float(f2tf32(x));
}

__device__ __forceinline__ void mma_tf32(float* d, const uint32_t* a,
                                         const uint32_t* b) {
    asm volatile(
        "mma.sync.aligned.m16n8k8.row.col.f32.tf32.tf32.f32 "
        "{%0,%1,%2,%3}, {%4,%5,%6,%7}, {%8,%9}, {%0,%1,%2,%3};"
        : "+f"(d[0]), "+f"(d[1]), "+f"(d[2]), "+f"(d[3])
        : "r"(a[0]), "r"(a[1]), "r"(a[2]), "r"(a[3]), "r"(b[0]), "r"(b[1]));
}

__device__ __forceinline__ void cpa16(uint32_t dst, const void* src) {
    asm volatile("cp.async.cg.shared.global [%0], [%1], 16;"
                 :: "r"(dst), "l"(src) : "memory");
}
#define CP_COMMIT() asm volatile("cp.async.commit_group;" ::: "memory")
#define CP_WAIT0()  asm volatile("cp.async.wait_group 0;" ::: "memory")
#define CP_WAIT1()  asm volatile("cp.async.wait_group 1;" ::: "memory")

// exp(x) for x <= 0 via FFMA-pipe exp2 polynomial (rel err <1e-5).
__device__ __forceinline__ float fexp(float x) {
    float t  = fmaxf(x, -87.0f) * 1.4426950408889634f;
    float fl = floorf(t);
    float f  = t - fl;
    float p  = 1.5403531e-4f;
    p = fmaf(p, f, 1.3333558e-3f);
    p = fmaf(p, f, 9.6181291e-3f);
    p = fmaf(p, f, 5.5504108e-2f);
    p = fmaf(p, f, 2.4022650e-1f);
    p = fmaf(p, f, 6.9314718e-1f);
    p = fmaf(p, f, 1.0f);
    int e = (int)fl;
    return __int_as_float((uint32_t)(e + 127) << 23) * p;
}

// ---------------------------------------------------------------------------
// Elementwise tf32-rounding pass (hidden states)
// ---------------------------------------------------------------------------
__global__ void round_kernel(const float4* __restrict__ in,
                             float4* __restrict__ out, int n4) {
    const int i = blockIdx.x * blockDim.x + threadIdx.x;
    if (i < n4) {
        float4 x = in[i];
        x.x = roundtf(x.x); x.y = roundtf(x.y);
        x.z = roundtf(x.z); x.w = roundtf(x.w);
        out[i] = x;
    }
}

// ---------------------------------------------------------------------------
// Weight transpose + tf32 round: out[C][R] = rna(in[R][C])
// ---------------------------------------------------------------------------
__global__ void transpose_kernel(const float* __restrict__ in,
                                 float* __restrict__ out, int R, int C) {
    __shared__ float t[32][33];
    const int bx = blockIdx.x * 32, by = blockIdx.y * 32;
    const int x = threadIdx.x, y = threadIdx.y;
#pragma unroll
    for (int j = 0; j < 32; j += 8)
        t[y + j][x] = in[(size_t)(by + y + j) * C + bx + x];
    __syncthreads();
#pragma unroll
    for (int j = 0; j < 32; j += 8)
        out[(size_t)(bx + y + j) * R + by + x] = roundtf(t[x][y + j]);
}

// ---------------------------------------------------------------------------
// V transpose + hi/lo tf32 split: vT[(b*4+hkv)][d][s]
// ---------------------------------------------------------------------------
__global__ void vtrans_kernel(const float* __restrict__ v,
                              float* __restrict__ vthi,
                              float* __restrict__ vtlo) {
    __shared__ float t[32][33];
    const int z = blockIdx.z;            // b*4 + hkv
    const int b = z >> 2, hkv = z & 3;
    const int s0 = blockIdx.y * 32, d0 = blockIdx.x * 32;
    const int x = threadIdx.x, y = threadIdx.y;
    const float* src = v + (size_t)b * Sq * 512 + hkv * 128;
#pragma unroll
    for (int j = 0; j < 32; j += 8)
        t[y + j][x] = src[(size_t)(s0 + y + j) * 512 + d0 + x];
    __syncthreads();
    float* dh = vthi + ((size_t)z * 128 + d0) * Sq + s0;
    float* dl = vtlo + ((size_t)z * 128 + d0) * Sq + s0;
#pragma unroll
    for (int j = 0; j < 32; j += 8) {
        const float val = t[x][y + j];
        const float hi = roundtf(val);
        dh[(size_t)(y + j) * Sq + x] = hi;
        dl[(size_t)(y + j) * Sq + x] = roundtf(val - hi);
    }
}

// ---------------------------------------------------------------------------
// TF32 mma.sync GEMM with cp.async 3-stage pipeline.
// Inputs pre-rounded to tf32 (rna) -> no cvt in the hot loop.
// CTA tile 128x128, BK=16, 8 warps (2x4), warp tile 64x32, occupancy 2.
// QKV=1: route output columns to q/k/v buffers.
// ---------------------------------------------------------------------------
#define SA   20
#define NST  3
#define STF  (128 * SA)                        // floats per stage per operand
#define GEMM_SMEM (NST * STF * 2 * 4)          // 61440 B

template <int QKV>
__global__ void __launch_bounds__(256, 2)
gemm_async(const float* __restrict__ A, const float* __restrict__ Bt, int K,
           float* __restrict__ C0, float* __restrict__ C1,
           float* __restrict__ C2) {
    extern __shared__ float sm[];
    const uint32_t smu = smem_to_u32(sm);

    const int tid = threadIdx.x;
    const int lane = tid & 31, wid = tid >> 5;
    const int wm = (wid & 1) * 64, wn = (wid >> 1) * 32;
    const int g = lane >> 2, tg = lane & 3;

    const int m0 = blockIdx.y * 128, n0 = blockIdx.x * 128;
    const float* Ab = A + (size_t)m0 * K;
    const float* Bb = Bt + (size_t)n0 * K;

    const int r0 = tid >> 2, r1 = r0 + 64;
    const int c4 = (tid & 3) * 4;

    const uint32_t stB = STF * 4;
    const uint32_t dA0 = smu + (uint32_t)(r0 * SA + c4) * 4;
    const uint32_t dA1 = smu + (uint32_t)(r1 * SA + c4) * 4;
    const uint32_t dB0 = smu + (uint32_t)(NST * STF + r0 * SA + c4) * 4;
    const uint32_t dB1 = dB0 + 64 * SA * 4;

    const int nk = K / 16;

    // Prologue: stages 0..NST-2
#pragma unroll
    for (int p = 0; p < NST - 1; p++) {
        const size_t kk = (size_t)p * 16 + c4;
        cpa16(dA0 + p * stB, Ab + (size_t)r0 * K + kk);
        cpa16(dA1 + p * stB, Ab + (size_t)r1 * K + kk);
        cpa16(dB0 + p * stB, Bb + (size_t)r0 * K + kk);
        cpa16(dB1 + p * stB, Bb + (size_t)r1 * K + kk);
        CP_COMMIT();
    }

    float acc[4][4][4];
#pragma unroll
    for (int mi = 0; mi < 4; mi++)
#pragma unroll
        for (int ni = 0; ni < 4; ni++)
#pragma unroll
            for (int e = 0; e < 4; e++) acc[mi][ni][e] = 0.f;

    for (int kt = 0; kt < nk; kt++) {
        CP_WAIT1();
        __syncthreads();

        const int kf = kt + NST - 1;
        if (kf < nk) {
            const int s = kf % NST;
            const size_t kk = (size_t)kf * 16 + c4;
            cpa16(dA0 + s * stB, Ab + (size_t)r0 * K + kk);
            cpa16(dA1 + s * stB, Ab + (size_t)r1 * K + kk);
            cpa16(dB0 + s * stB, Bb + (size_t)r0 * K + kk);
            cpa16(dB1 + s * stB, Bb + (size_t)r1 * K + kk);
        }
        CP_COMMIT();

        const float* as = sm + (kt % NST) * STF;
        const float* bs = sm + NST * STF + (kt % NST) * STF;
#pragma unroll
        for (int ks = 0; ks < 2; ks++) {
            const int kb = ks * 8;
            uint32_t af[4][4], bf[4][2];
#pragma unroll
            for (int mi = 0; mi < 4; mi++) {
                const float* p = &as[(wm + mi * 16 + g) * SA + kb + tg];
                af[mi][0] = __float_as_uint(p[0]);
                af[mi][1] = __float_as_uint(p[8 * SA]);
                af[mi][2] = __float_as_uint(p[4]);
                af[mi][3] = __float_as_uint(p[8 * SA + 4]);
            }
#pragma unroll
            for (int ni = 0; ni < 4; ni++) {
                const float* p = &bs[(wn + ni * 8 + g) * SA + kb + tg];
                bf[ni][0] = __float_as_uint(p[0]);
                bf[ni][1] = __float_as_uint(p[4]);
            }
#pragma unroll
            for (int mi = 0; mi < 4; mi++)
#pragma unroll
                for (int ni = 0; ni < 4; ni++)
                    mma_tf32(acc[mi][ni], af[mi], bf[ni]);
        }
    }

    // Epilogue with output routing
    float* C;
    int ldc, col0;
    if (QKV) {
        if (n0 < 2048)      { C = C0; ldc = 2048; col0 = n0; }
        else if (n0 < 2560) { C = C1; ldc = 512;  col0 = n0 - 2048; }
        else                { C = C2; ldc = 512;  col0 = n0 - 2560; }
    } else {
        C = C0; ldc = 2048; col0 = n0;
    }
#pragma unroll
    for (int mi = 0; mi < 4; mi++) {
        const int row0 = m0 + wm + mi * 16 + g;
#pragma unroll
        for (int ni = 0; ni < 4; ni++) {
            const int col = col0 + wn + ni * 8 + tg * 2;
            *(float2*)&C[(size_t)row0 * ldc + col] =
                make_float2(acc[mi][ni][0], acc[mi][ni][1]);
            *(float2*)&C[(size_t)(row0 + 8) * ldc + col] =
                make_float2(acc[mi][ni][2], acc[mi][ni][3]);
        }
    }
}

// ---------------------------------------------------------------------------
// Fused RMSNorm + RoPE; output scaled by outscale and tf32-rounded.
// ---------------------------------------------------------------------------
__global__ void rmsnorm_rope_kernel(float* __restrict__ x,
                                    const float* __restrict__ w,
                                    const float* __restrict__ cosb,
                                    const float* __restrict__ sinb,
                                    int nheads, float outscale) {
    const int idx = blockIdx.x;
    const int s   = (idx / nheads) % Sq;
    const int d   = threadIdx.x;
    float* row    = x + (size_t)idx * Dh;

    float v  = row[d];
    float ss = v * v;
#pragma unroll
    for (int off = 16; off > 0; off >>= 1)
        ss += __shfl_xor_sync(0xffffffffu, ss, off);

    __shared__ float red[4];
    if ((d & 31) == 0) red[d >> 5] = ss;
    __syncthreads();
    float tot  = red[0] + red[1] + red[2] + red[3];
    float rinv = rsqrtf(tot / Dh + 1e-6f);
    float xn   = v * rinv * w[d];

    __shared__ float smv[Dh];
    smv[d] = xn;
    __syncthreads();
    float rot = (d < Dh / 2) ? -smv[d + Dh / 2] : smv[d - Dh / 2];
    float c   = cosb[(size_t)s * Dh + d];
    float sn  = sinb[(size_t)s * Dh + d];
    row[d]    = roundtf((xn * c + rot * sn) * outscale);
}

// ---------------------------------------------------------------------------
// Flash attention, tf32 mma. BQ=128 (8 warps x 16 rows), BKV=64.
// Q: pre-scaled + pre-rounded. K: pre-rounded, single tf32 MMA.
// V: pre-transposed + hi/lo split (2 MMAs). All tile loads via cp.async.
// ---------------------------------------------------------------------------
#define FBQ  128
#define FBKV 64
#define QS_S 132
#define KS_S 132
#define VS_S 68
#define PS_S 68
#define OFF_Q  0
#define OFF_K  (FBQ * QS_S)                   // 16896
#define OFF_VH (OFF_K + FBKV * KS_S)          // 25344
#define OFF_VL (OFF_VH + Dh * VS_S)           // 34048
#define OFF_P  (OFF_VL + Dh * VS_S)           // 42752
#define FLASH_SMEM ((OFF_P + FBQ * PS_S) * 4) // 205824 B

__global__ void __launch_bounds__(256, 1)
flash_mma_kernel(const float* __restrict__ q,
                 const float* __restrict__ k,
                 const float* __restrict__ vth,
                 const float* __restrict__ vtl,
                 float* __restrict__ ctx) {
    extern __shared__ float fs[];
    const uint32_t fsb = smem_to_u32(fs);
    const uint32_t* fsu = (const uint32_t*)fs;
    uint32_t* fsw = (uint32_t*)fs;

    const int bh  = blockIdx.y;
    const int b   = bh / HQn;
    const int h   = bh % HQn;
    const int hkv = h / NREP;
    const int q0  = (gridDim.x - 1 - blockIdx.x) * FBQ;

    const int tid  = threadIdx.x;
    const int lane = tid & 31, wid = tid >> 5;
    const int g = lane >> 2, tg = lane & 3;
    const int wband = wid * 16;

    // Q tile via cp.async (joins first tile's commit group)
    const float* qbase = q + (((size_t)b * Sq + q0) * HQn + h) * Dh;
#pragma unroll
    for (int j = 0; j < 16; j++) {
        const int idx = tid + j * 256;
        const int r = idx >> 5, c = (idx & 31) * 4;
        cpa16(fsb + (uint32_t)(OFF_Q + r * QS_S + c) * 4,
              qbase + (size_t)r * HQn * Dh + c);
    }

    float m[2], l[2], O[16][4];
    m[0] = m[1] = -1e30f;
    l[0] = l[1] = 0.f;
#pragma unroll
    for (int nt = 0; nt < 16; nt++)
#pragma unroll
        for (int e = 0; e < 4; e++) O[nt][e] = 0.f;

    const float* kbase = k + ((size_t)b * Sq * HKVn + hkv) * Dh;
    const float* vhb = vth + (size_t)(b * HKVn + hkv) * Dh * Sq;
    const float* vlb = vtl + (size_t)(b * HKVn + hkv) * Dh * Sq;

    const int kend = q0 + FBQ;
    for (int k0 = 0; k0 < kend; k0 += FBKV) {
        __syncthreads();   // previous tile's PV done before overwriting K/V

        // K tile (64 x 128)
#pragma unroll
        for (int j = 0; j < 8; j++) {
            const int idx = tid + j * 256;
            const int r = idx >> 5, c = (idx & 31) * 4;
            cpa16(fsb + (uint32_t)(OFF_K + r * KS_S + c) * 4,
                  kbase + (size_t)(k0 + r) * HKVn * Dh + c);
        }
        // V^T hi/lo tiles (128 x 64)
#pragma unroll
        for (int j = 0; j < 8; j++) {
            const int idx = tid + j * 256;
            const int r = idx >> 4, c = (idx & 15) * 4;
            cpa16(fsb + (uint32_t)(OFF_VH + r * VS_S + c) * 4,
                  vhb + (size_t)r * Sq + k0 + c);
            cpa16(fsb + (uint32_t)(OFF_VL + r * VS_S + c) * 4,
                  vlb + (size_t)r * Sq + k0 + c);
        }
        CP_COMMIT();
        CP_WAIT0();
        __syncthreads();

        // ---- Scores: single tf32 MMA per fragment ----
        float sc[8][4];
#pragma unroll
        for (int nt = 0; nt < 8; nt++)
#pragma unroll
            for (int e = 0; e < 4; e++) sc[nt][e] = 0.f;

#pragma unroll
        for (int ks = 0; ks < 16; ks++) {
            const int kb = ks * 8;
            uint32_t a[4];
            {
                const uint32_t* p = &fsu[OFF_Q + (wband + g) * QS_S + kb + tg];
                a[0] = p[0];
                a[1] = p[8 * QS_S];
                a[2] = p[4];
                a[3] = p[8 * QS_S + 4];
            }
#pragma unroll
            for (int nt = 0; nt < 8; nt++) {
                const uint32_t* pk = &fsu[OFF_K + (nt * 8 + g) * KS_S + kb + tg];
                uint32_t bb[2] = {pk[0], pk[4]};
                mma_tf32(sc[nt], a, bb);
            }
        }

        // Causal mask (tiles intersecting the diagonal)
        if (k0 + FBKV - 1 > q0) {
#pragma unroll
            for (int nt = 0; nt < 8; nt++)
#pragma unroll
                for (int e = 0; e < 4; e++) {
                    const int qg = q0 + wband + g + ((e >> 1) << 3);
                    const int kg = k0 + nt * 8 + tg * 2 + (e & 1);
                    if (kg > qg) sc[nt][e] = -1e30f;
                }
        }

        // ---- Online softmax (rows g and g+8; 4 lanes share each row) ----
        float corr[2];
#pragma unroll
        for (int r2 = 0; r2 < 2; r2++) {
            float tm = -1e30f;
#pragma unroll
            for (int nt = 0; nt < 8; nt++)
                tm = fmaxf(tm, fmaxf(sc[nt][r2 * 2], sc[nt][r2 * 2 + 1]));
            tm = fmaxf(tm, __shfl_xor_sync(0xffffffffu, tm, 1));
            tm = fmaxf(tm, __shfl_xor_sync(0xffffffffu, tm, 2));
            const float mn = fmaxf(m[r2], tm);
            corr[r2] = fexp(m[r2] - mn);
            m[r2] = mn;
            float s2 = 0.f;
            const int prow = (wband + g + r2 * 8) * PS_S;
#pragma unroll
            for (int nt = 0; nt < 8; nt++) {
                float p0 = fexp(sc[nt][r2 * 2]     - mn);
                float p1 = fexp(sc[nt][r2 * 2 + 1] - mn);
                uint32_t t0 = f2tf32(p0), t1 = f2tf32(p1);
                s2 += __uint_as_float(t0) + __uint_as_float(t1);
                *(uint2*)&fsw[OFF_P + prow + nt * 8 + tg * 2] =
                    make_uint2(t0, t1);
            }
            s2 += __shfl_xor_sync(0xffffffffu, s2, 1);
            s2 += __shfl_xor_sync(0xffffffffu, s2, 2);
            l[r2] = l[r2] * corr[r2] + s2;
        }

#pragma unroll
        for (int nt = 0; nt < 16; nt++) {
            O[nt][0] *= corr[0]; O[nt][1] *= corr[0];
            O[nt][2] *= corr[1]; O[nt][3] *= corr[1];
        }
        __syncwarp();   // own-warp P rows visible to own warp

        // ---- PV: O += P @ V (V hi/lo split) ----
#pragma unroll
        for (int ks = 0; ks < 8; ks++) {
            const int kb = ks * 8;
            uint32_t a[4];
            {
                const uint32_t* p = &fsu[OFF_P + (wband + g) * PS_S + kb + tg];
                a[0] = p[0];
                a[1] = p[8 * PS_S];
                a[2] = p[4];
                a[3] = p[8 * PS_S + 4];
            }
#pragma unroll
            for (int nt = 0; nt < 16; nt++) {
                const uint32_t* ph = &fsu[OFF_VH + (nt * 8 + g) * VS_S + kb + tg];
                const uint32_t* pl = &fsu[OFF_VL + (nt * 8 + g) * VS_S + kb + tg];
                uint32_t bh_[2] = {ph[0], ph[4]};
                uint32_t bl_[2] = {pl[0], pl[4]};
                mma_tf32(O[nt], a, bh_);
                mma_tf32(O[nt], a, bl_);
            }
        }
    }

    // ---- Write output (tf32-rounded: feeds the O-projection GEMM) ----
    const float inv0 = 1.f / l[0];
    const float inv1 = 1.f / l[1];
    const int row0 = q0 + wband + g;
    float* base0 = ctx + (((size_t)b * Sq + row0) * HQn + h) * Dh;
    float* base1 = base0 + (size_t)8 * HQn * Dh;
#pragma unroll
    for (int nt = 0; nt < 16; nt++) {
        const int col = nt * 8 + tg * 2;
        *(float2*)&base0[col] = make_float2(roundtf(O[nt][0] * inv0),
                                            roundtf(O[nt][1] * inv0));
        *(float2*)&base1[col] = make_float2(roundtf(O[nt][2] * inv1),
                                            roundtf(O[nt][3] * inv1));
    }
}

// ---------------------------------------------------------------------------
// Launch
// ---------------------------------------------------------------------------
extern "C" void kernel_launch(void* const* d_in, const int* in_sizes, int n_in,
                              void* d_out, int out_size) {
    const float* hidden = (const float*)d_in[0];
    const float* cosb   = (const float*)d_in[1];
    const float* sinb   = (const float*)d_in[2];
    const float* Wq = (const float*)d_in[4];
    const float* Wk = (const float*)d_in[5];
    const float* Wv = (const float*)d_in[6];
    const float* Wo = (const float*)d_in[7];
    const float* qw = (const float*)d_in[8];
    const float* kw = (const float*)d_in[9];
    float* out = (float*)d_out;

    float *qb, *kb, *vb, *cb, *hidR, *wqkvT, *woT, *vthi, *vtlo;
    cudaGetSymbolAddress((void**)&qb, g_q);
    cudaGetSymbolAddress((void**)&kb, g_k);
    cudaGetSymbolAddress((void**)&vb, g_v);
    cudaGetSymbolAddress((void**)&cb, g_ctx);
    cudaGetSymbolAddress((void**)&hidR, g_hidR);
    cudaGetSymbolAddress((void**)&wqkvT, g_WqkvT);
    cudaGetSymbolAddress((void**)&woT, g_WoT);
    cudaGetSymbolAddress((void**)&vthi, g_vThi);
    cudaGetSymbolAddress((void**)&vtlo, g_vTlo);

    const int M = Bq * Sq;  // 4096
    const float scale = 0.088388347648318447f;  // 1/sqrt(128)

    // Pre-round hidden states to tf32 (rna)
    round_kernel<<<(M * Hd / 4 + 255) / 256, 256>>>(
        (const float4*)hidden, (float4*)hidR, M * Hd / 4);

    // Weight transposes + rounding. WqkvT rows: [0,2048)=Wq, [2048,2560)=Wk,
    // [2560,3072)=Wv.
    transpose_kernel<<<dim3(64, 64), dim3(32, 8)>>>(Wq, wqkvT, 2048, 2048);
    transpose_kernel<<<dim3(16, 64), dim3(32, 8)>>>(
        Wk, wqkvT + (size_t)2048 * 2048, 2048, 512);
    transpose_kernel<<<dim3(16, 64), dim3(32, 8)>>>(
        Wv, wqkvT + (size_t)2560 * 2048, 2048, 512);
    transpose_kernel<<<dim3(64, 64), dim3(32, 8)>>>(Wo, woT, 2048, 2048);

    cudaFuncSetAttribute(gemm_async<1>,
                         cudaFuncAttributeMaxDynamicSharedMemorySize, GEMM_SMEM);
    cudaFuncSetAttribute(gemm_async<0>,
                         cudaFuncAttributeMaxDynamicSharedMemorySize, GEMM_SMEM);

    // Fused QKV projection
    gemm_async<1><<<dim3(24, 32), 256, GEMM_SMEM>>>(
        hidR, wqkvT, Hd, qb, kb, vb);

    // RMSNorm + RoPE (q pre-scaled by 1/sqrt(d); both tf32-rounded)
    rmsnorm_rope_kernel<<<Bq * Sq * HQn, Dh>>>(qb, qw, cosb, sinb, HQn, scale);
    rmsnorm_rope_kernel<<<Bq * Sq * HKVn, Dh>>>(kb, kw, cosb, sinb, HKVn, 1.0f);

    // V transpose + hi/lo split
    vtrans_kernel<<<dim3(4, 64, Bq * HKVn), dim3(32, 8)>>>(vb, vthi, vtlo);

    // Flash attention
    cudaFuncSetAttribute(flash_mma_kernel,
                         cudaFuncAttributeMaxDynamicSharedMemorySize, FLASH_SMEM);
    flash_mma_kernel<<<dim3(Sq / FBQ, Bq * HQn), 256, FLASH_SMEM>>>(
        qb, kb, vthi, vtlo, cb);

    // Output projection
    gemm_async<0><<<dim3(16, 32), 256, GEMM_SMEM>>>(
        cb, woT, HQn * Dh, out, nullptr, nullptr);
}

// round 6
// speedup vs baseline: 4.1131x; 1.1144x over previous
#include <cuda_runtime.h>
#include <cstdint>

// Problem constants (fixed by the dataset)
#define Bq   2
#define Sq   2048
#define Hd   2048
#define HQn  16
#define HKVn 4
#define Dh   128
#define NREP (HQn / HKVn)

// Scratch (device globals; no runtime allocation allowed)
__device__ float g_q[(size_t)Bq * Sq * HQn * Dh];     // 32 MB
__device__ float g_k[(size_t)Bq * Sq * HKVn * Dh];    // 8 MB
__device__ float g_v[(size_t)Bq * Sq * HKVn * Dh];    // 8 MB
__device__ float g_ctx[(size_t)Bq * Sq * HQn * Dh];   // 32 MB
__device__ float g_hidR[(size_t)Bq * Sq * Hd];        // 32 MB (rounded hidden)
__device__ float g_WqkvT[(size_t)3072 * 2048];        // 24 MB (rounded, transposed)
__device__ float g_WoT[(size_t)2048 * 2048];          // 16 MB (rounded, transposed)
__device__ float g_vT[(size_t)Bq * HKVn * Dh * Sq];   // 8 MB (V^T, tf32-rounded)

// ---------------------------------------------------------------------------
// Helpers
// ---------------------------------------------------------------------------
__device__ __forceinline__ uint32_t smem_to_u32(const void* p) {
    uint32_t a;
    asm("{ .reg .u64 t; cvta.to.shared.u64 t, %1; cvt.u32.u64 %0, t; }"
        : "=r"(a) : "l"(p));
    return a;
}

__device__ __forceinline__ uint32_t f2tf32(float x) {
    uint32_t u;
    asm("cvt.rna.tf32.f32 %0, %1;" : "=r"(u) : "f"(x));
    return u;
}
__device__ __forceinline__ float roundtf(float x) {
    return __uint_as_float(f2tf32(x));
}

__device__ __forceinline__ void mma_tf32(float* d, const uint32_t* a,
                                         const uint32_t* b) {
    asm volatile(
        "mma.sync.aligned.m16n8k8.row.col.f32.tf32.tf32.f32 "
        "{%0,%1,%2,%3}, {%4,%5,%6,%7}, {%8,%9}, {%0,%1,%2,%3};"
        : "+f"(d[0]), "+f"(d[1]), "+f"(d[2]), "+f"(d[3])
        : "r"(a[0]), "r"(a[1]), "r"(a[2]), "r"(a[3]), "r"(b[0]), "r"(b[1]));
}

__device__ __forceinline__ void cpa16(uint32_t dst, const void* src) {
    asm volatile("cp.async.cg.shared.global [%0], [%1], 16;"
                 :: "r"(dst), "l"(src) : "memory");
}
#define CP_COMMIT() asm volatile("cp.async.commit_group;" ::: "memory")
#define CP_WAIT0()  asm volatile("cp.async.wait_group 0;" ::: "memory")
#define CP_WAIT1()  asm volatile("cp.async.wait_group 1;" ::: "memory")

// exp(x) for x <= 0 via FFMA-pipe exp2 polynomial (rel err <1e-5).
__device__ __forceinline__ float fexp(float x) {
    float t  = fmaxf(x, -87.0f) * 1.4426950408889634f;
    float fl = floorf(t);
    float f  = t - fl;
    float p  = 1.5403531e-4f;
    p = fmaf(p, f, 1.3333558e-3f);
    p = fmaf(p, f, 9.6181291e-3f);
    p = fmaf(p, f, 5.5504108e-2f);
    p = fmaf(p, f, 2.4022650e-1f);
    p = fmaf(p, f, 6.9314718e-1f);
    p = fmaf(p, f, 1.0f);
    int e = (int)fl;
    return __int_as_float((uint32_t)(e + 127) << 23) * p;
}

// ---------------------------------------------------------------------------
// Elementwise tf32-rounding pass (hidden states)
// ---------------------------------------------------------------------------
__global__ void round_kernel(const float4* __restrict__ in,
                             float4* __restrict__ out, int n4) {
    const int i = blockIdx.x * blockDim.x + threadIdx.x;
    if (i < n4) {
        float4 x = in[i];
        x.x = roundtf(x.x); x.y = roundtf(x.y);
        x.z = roundtf(x.z); x.w = roundtf(x.w);
        out[i] = x;
    }
}

// ---------------------------------------------------------------------------
// Weight transpose + tf32 round: out[C][R] = rna(in[R][C])
// ---------------------------------------------------------------------------
__global__ void transpose_kernel(const float* __restrict__ in,
                                 float* __restrict__ out, int R, int C) {
    __shared__ float t[32][33];
    const int bx = blockIdx.x * 32, by = blockIdx.y * 32;
    const int x = threadIdx.x, y = threadIdx.y;
#pragma unroll
    for (int j = 0; j < 32; j += 8)
        t[y + j][x] = in[(size_t)(by + y + j) * C + bx + x];
    __syncthreads();
#pragma unroll
    for (int j = 0; j < 32; j += 8)
        out[(size_t)(bx + y + j) * R + by + x] = roundtf(t[x][y + j]);
}

// ---------------------------------------------------------------------------
// V transpose + tf32 round: vT[(b*4+hkv)][d][s]
// ---------------------------------------------------------------------------
__global__ void vtrans_kernel(const float* __restrict__ v,
                              float* __restrict__ vt) {
    __shared__ float t[32][33];
    const int z = blockIdx.z;            // b*4 + hkv
    const int b = z >> 2, hkv = z & 3;
    const int s0 = blockIdx.y * 32, d0 = blockIdx.x * 32;
    const int x = threadIdx.x, y = threadIdx.y;
    const float* src = v + (size_t)b * Sq * 512 + hkv * 128;
#pragma unroll
    for (int j = 0; j < 32; j += 8)
        t[y + j][x] = src[(size_t)(s0 + y + j) * 512 + d0 + x];
    __syncthreads();
    float* dst = vt + ((size_t)z * 128 + d0) * Sq + s0;
#pragma unroll
    for (int j = 0; j < 32; j += 8)
        dst[(size_t)(y + j) * Sq + x] = roundtf(t[x][y + j]);
}

// ---------------------------------------------------------------------------
// TF32 mma.sync GEMM with cp.async 3-stage pipeline (round-5, passing).
// ---------------------------------------------------------------------------
#define SA   20
#define NST  3
#define STF  (128 * SA)
#define GEMM_SMEM (NST * STF * 2 * 4)          // 61440 B

template <int QKV>
__global__ void __launch_bounds__(256, 2)
gemm_async(const float* __restrict__ A, const float* __restrict__ Bt, int K,
           float* __restrict__ C0, float* __restrict__ C1,
           float* __restrict__ C2) {
    extern __shared__ float sm[];
    const uint32_t smu = smem_to_u32(sm);

    const int tid = threadIdx.x;
    const int lane = tid & 31, wid = tid >> 5;
    const int wm = (wid & 1) * 64, wn = (wid >> 1) * 32;
    const int g = lane >> 2, tg = lane & 3;

    const int m0 = blockIdx.y * 128, n0 = blockIdx.x * 128;
    const float* Ab = A + (size_t)m0 * K;
    const float* Bb = Bt + (size_t)n0 * K;

    const int r0 = tid >> 2, r1 = r0 + 64;
    const int c4 = (tid & 3) * 4;

    const uint32_t stB = STF * 4;
    const uint32_t dA0 = smu + (uint32_t)(r0 * SA + c4) * 4;
    const uint32_t dA1 = smu + (uint32_t)(r1 * SA + c4) * 4;
    const uint32_t dB0 = smu + (uint32_t)(NST * STF + r0 * SA + c4) * 4;
    const uint32_t dB1 = dB0 + 64 * SA * 4;

    const int nk = K / 16;

#pragma unroll
    for (int p = 0; p < NST - 1; p++) {
        const size_t kk = (size_t)p * 16 + c4;
        cpa16(dA0 + p * stB, Ab + (size_t)r0 * K + kk);
        cpa16(dA1 + p * stB, Ab + (size_t)r1 * K + kk);
        cpa16(dB0 + p * stB, Bb + (size_t)r0 * K + kk);
        cpa16(dB1 + p * stB, Bb + (size_t)r1 * K + kk);
        CP_COMMIT();
    }

    float acc[4][4][4];
#pragma unroll
    for (int mi = 0; mi < 4; mi++)
#pragma unroll
        for (int ni = 0; ni < 4; ni++)
#pragma unroll
            for (int e = 0; e < 4; e++) acc[mi][ni][e] = 0.f;

    for (int kt = 0; kt < nk; kt++) {
        CP_WAIT1();
        __syncthreads();

        const int kf = kt + NST - 1;
        if (kf < nk) {
            const int s = kf % NST;
            const size_t kk = (size_t)kf * 16 + c4;
            cpa16(dA0 + s * stB, Ab + (size_t)r0 * K + kk);
            cpa16(dA1 + s * stB, Ab + (size_t)r1 * K + kk);
            cpa16(dB0 + s * stB, Bb + (size_t)r0 * K + kk);
            cpa16(dB1 + s * stB, Bb + (size_t)r1 * K + kk);
        }
        CP_COMMIT();

        const float* as = sm + (kt % NST) * STF;
        const float* bs = sm + NST * STF + (kt % NST) * STF;
#pragma unroll
        for (int ks = 0; ks < 2; ks++) {
            const int kb = ks * 8;
            uint32_t af[4][4], bf[4][2];
#pragma unroll
            for (int mi = 0; mi < 4; mi++) {
                const float* p = &as[(wm + mi * 16 + g) * SA + kb + tg];
                af[mi][0] = __float_as_uint(p[0]);
                af[mi][1] = __float_as_uint(p[8 * SA]);
                af[mi][2] = __float_as_uint(p[4]);
                af[mi][3] = __float_as_uint(p[8 * SA + 4]);
            }
#pragma unroll
            for (int ni = 0; ni < 4; ni++) {
                const float* p = &bs[(wn + ni * 8 + g) * SA + kb + tg];
                bf[ni][0] = __float_as_uint(p[0]);
                bf[ni][1] = __float_as_uint(p[4]);
            }
#pragma unroll
            for (int mi = 0; mi < 4; mi++)
#pragma unroll
                for (int ni = 0; ni < 4; ni++)
                    mma_tf32(acc[mi][ni], af[mi], bf[ni]);
        }
    }

    float* C;
    int ldc, col0;
    if (QKV) {
        if (n0 < 2048)      { C = C0; ldc = 2048; col0 = n0; }
        else if (n0 < 2560) { C = C1; ldc = 512;  col0 = n0 - 2048; }
        else                { C = C2; ldc = 512;  col0 = n0 - 2560; }
    } else {
        C = C0; ldc = 2048; col0 = n0;
    }
#pragma unroll
    for (int mi = 0; mi < 4; mi++) {
        const int row0 = m0 + wm + mi * 16 + g;
#pragma unroll
        for (int ni = 0; ni < 4; ni++) {
            const int col = col0 + wn + ni * 8 + tg * 2;
            *(float2*)&C[(size_t)row0 * ldc + col] =
                make_float2(acc[mi][ni][0], acc[mi][ni][1]);
            *(float2*)&C[(size_t)(row0 + 8) * ldc + col] =
                make_float2(acc[mi][ni][2], acc[mi][ni][3]);
        }
    }
}

// ---------------------------------------------------------------------------
// Fused RMSNorm + RoPE; output scaled by outscale and tf32-rounded.
// ---------------------------------------------------------------------------
__global__ void rmsnorm_rope_kernel(float* __restrict__ x,
                                    const float* __restrict__ w,
                                    const float* __restrict__ cosb,
                                    const float* __restrict__ sinb,
                                    int nheads, float outscale) {
    const int idx = blockIdx.x;
    const int s   = (idx / nheads) % Sq;
    const int d   = threadIdx.x;
    float* row    = x + (size_t)idx * Dh;

    float v  = row[d];
    float ss = v * v;
#pragma unroll
    for (int off = 16; off > 0; off >>= 1)
        ss += __shfl_xor_sync(0xffffffffu, ss, off);

    __shared__ float red[4];
    if ((d & 31) == 0) red[d >> 5] = ss;
    __syncthreads();
    float tot  = red[0] + red[1] + red[2] + red[3];
    float rinv = rsqrtf(tot / Dh + 1e-6f);
    float xn   = v * rinv * w[d];

    __shared__ float smv[Dh];
    smv[d] = xn;
    __syncthreads();
    float rot = (d < Dh / 2) ? -smv[d + Dh / 2] : smv[d - Dh / 2];
    float c   = cosb[(size_t)s * Dh + d];
    float sn  = sinb[(size_t)s * Dh + d];
    row[d]    = roundtf((xn * c + rot * sn) * outscale);
}

// ---------------------------------------------------------------------------
// Flash attention, tf32 mma, double-buffered K/V via cp.async.
// BQ=128 (8 warps x 16 rows), BKV=64.
// Q pre-scaled+rounded; K pre-rounded (1 MMA); V^T pre-rounded (1 MMA).
// P aliases the CURRENT K stage (K dead after scores; stage sized for P).
// ---------------------------------------------------------------------------
#define FBQ   128
#define FBKV  64
#define QS_S  132
#define KS_S  140                     // 140 % 32 = 12 -> conflict-free frags
#define VS_S  68
#define PS_S  68
#define K_STG (FBKV * KS_S)           // 8960 floats (>= P size 8704)
#define V_STG (Dh * VS_S)             // 8704 floats
#define OFF_Q  0
#define OFF_K0 (FBQ * QS_S)           // 16896
#define OFF_V0 (OFF_K0 + 2 * K_STG)   // 34816
#define FLASH_SMEM ((OFF_V0 + 2 * V_STG) * 4)   // 208896 B

__global__ void __launch_bounds__(256, 1)
flash_mma_kernel(const float* __restrict__ q,
                 const float* __restrict__ k,
                 const float* __restrict__ vt,
                 float* __restrict__ ctx) {
    extern __shared__ float fs[];
    const uint32_t fsb = smem_to_u32(fs);
    const uint32_t* fsu = (const uint32_t*)fs;
    uint32_t* fsw = (uint32_t*)fs;

    const int bh  = blockIdx.y;
    const int b   = bh / HQn;
    const int h   = bh % HQn;
    const int hkv = h / NREP;
    const int q0  = (gridDim.x - 1 - blockIdx.x) * FBQ;

    const int tid  = threadIdx.x;
    const int lane = tid & 31, wid = tid >> 5;
    const int g = lane >> 2, tg = lane & 3;
    const int wband = wid * 16;

    const float* kbase = k + ((size_t)b * Sq * HKVn + hkv) * Dh;
    const float* vbase = vt + (size_t)(b * HKVn + hkv) * Dh * Sq;

    // Prologue: Q tile + KV tile 0, one commit group.
    const float* qbase = q + (((size_t)b * Sq + q0) * HQn + h) * Dh;
#pragma unroll
    for (int j = 0; j < 16; j++) {
        const int idx = tid + j * 256;
        const int r = idx >> 5, c = (idx & 31) * 4;
        cpa16(fsb + (uint32_t)(OFF_Q + r * QS_S + c) * 4,
              qbase + (size_t)r * HQn * Dh + c);
    }
#pragma unroll
    for (int j = 0; j < 8; j++) {
        const int idx = tid + j * 256;
        const int rk = idx >> 5, ck = (idx & 31) * 4;
        cpa16(fsb + (uint32_t)(OFF_K0 + rk * KS_S + ck) * 4,
              kbase + (size_t)rk * HKVn * Dh + ck);
        const int rv = idx >> 4, cv = (idx & 15) * 4;
        cpa16(fsb + (uint32_t)(OFF_V0 + rv * VS_S + cv) * 4,
              vbase + (size_t)rv * Sq + cv);
    }
    CP_COMMIT();

    float m[2], l[2], O[16][4];
    m[0] = m[1] = -1e30f;
    l[0] = l[1] = 0.f;
#pragma unroll
    for (int nt = 0; nt < 16; nt++)
#pragma unroll
        for (int e = 0; e < 4; e++) O[nt][e] = 0.f;

    const int ntile = (q0 + FBQ) / FBKV;
    for (int i = 0; i < ntile; i++) {
        const int st = i & 1;
        const int offK = OFF_K0 + st * K_STG;
        const int offV = OFF_V0 + st * V_STG;

        CP_WAIT0();          // KV[i] (+Q on i=0) arrived
        __syncthreads();     // all warps: prev PV done -> other stage free

        // Prefetch KV[i+1] into the other stage.
        if (i + 1 < ntile) {
            const int k0n = (i + 1) * FBKV;
            const int offKn = OFF_K0 + (st ^ 1) * K_STG;
            const int offVn = OFF_V0 + (st ^ 1) * V_STG;
#pragma unroll
            for (int j = 0; j < 8; j++) {
                const int idx = tid + j * 256;
                const int rk = idx >> 5, ck = (idx & 31) * 4;
                cpa16(fsb + (uint32_t)(offKn + rk * KS_S + ck) * 4,
                      kbase + (size_t)(k0n + rk) * HKVn * Dh + ck);
                const int rv = idx >> 4, cv = (idx & 15) * 4;
                cpa16(fsb + (uint32_t)(offVn + rv * VS_S + cv) * 4,
                      vbase + (size_t)rv * Sq + k0n + cv);
            }
        }
        CP_COMMIT();

        // ---- Scores ----
        float sc[8][4];
#pragma unroll
        for (int nt = 0; nt < 8; nt++)
#pragma unroll
            for (int e = 0; e < 4; e++) sc[nt][e] = 0.f;

#pragma unroll
        for (int ks = 0; ks < 16; ks++) {
            const int kb = ks * 8;
            uint32_t a[4];
            {
                const uint32_t* p = &fsu[OFF_Q + (wband + g) * QS_S + kb + tg];
                a[0] = p[0];
                a[1] = p[8 * QS_S];
                a[2] = p[4];
                a[3] = p[8 * QS_S + 4];
            }
#pragma unroll
            for (int nt = 0; nt < 8; nt++) {
                const uint32_t* pk = &fsu[offK + (nt * 8 + g) * KS_S + kb + tg];
                uint32_t bb[2] = {pk[0], pk[4]};
                mma_tf32(sc[nt], a, bb);
            }
        }

        // Causal mask (tiles intersecting the diagonal)
        const int k0 = i * FBKV;
        if (k0 + FBKV - 1 > q0) {
#pragma unroll
            for (int nt = 0; nt < 8; nt++)
#pragma unroll
                for (int e = 0; e < 4; e++) {
                    const int qg = q0 + wband + g + ((e >> 1) << 3);
                    const int kg = k0 + nt * 8 + tg * 2 + (e & 1);
                    if (kg > qg) sc[nt][e] = -1e30f;
                }
        }

        __syncthreads();   // all warps done reading K[st] before P overwrites it

        // ---- Online softmax (rows g and g+8; 4 lanes share each row) ----
        float corr[2];
#pragma unroll
        for (int r2 = 0; r2 < 2; r2++) {
            float tm = -1e30f;
#pragma unroll
            for (int nt = 0; nt < 8; nt++)
                tm = fmaxf(tm, fmaxf(sc[nt][r2 * 2], sc[nt][r2 * 2 + 1]));
            tm = fmaxf(tm, __shfl_xor_sync(0xffffffffu, tm, 1));
            tm = fmaxf(tm, __shfl_xor_sync(0xffffffffu, tm, 2));
            const float mn = fmaxf(m[r2], tm);
            corr[r2] = fexp(m[r2] - mn);
            m[r2] = mn;
            float s2 = 0.f;
            const int prow = offK + (wband + g + r2 * 8) * PS_S;
#pragma unroll
            for (int nt = 0; nt < 8; nt++) {
                float p0 = fexp(sc[nt][r2 * 2]     - mn);
                float p1 = fexp(sc[nt][r2 * 2 + 1] - mn);
                uint32_t t0 = f2tf32(p0), t1 = f2tf32(p1);
                s2 += __uint_as_float(t0) + __uint_as_float(t1);
                *(uint2*)&fsw[prow + nt * 8 + tg * 2] = make_uint2(t0, t1);
            }
            s2 += __shfl_xor_sync(0xffffffffu, s2, 1);
            s2 += __shfl_xor_sync(0xffffffffu, s2, 2);
            l[r2] = l[r2] * corr[r2] + s2;
        }

#pragma unroll
        for (int nt = 0; nt < 16; nt++) {
            O[nt][0] *= corr[0]; O[nt][1] *= corr[0];
            O[nt][2] *= corr[1]; O[nt][3] *= corr[1];
        }
        __syncwarp();   // own-warp P rows visible to own warp

        // ---- PV: O += P @ V (single tf32 MMA per fragment) ----
#pragma unroll
        for (int ks = 0; ks < 8; ks++) {
            const int kb = ks * 8;
            uint32_t a[4];
            {
                const uint32_t* p = &fsu[offK + (wband + g) * PS_S + kb + tg];
                a[0] = p[0];
                a[1] = p[8 * PS_S];
                a[2] = p[4];
                a[3] = p[8 * PS_S + 4];
            }
#pragma unroll
            for (int nt = 0; nt < 16; nt++) {
                const uint32_t* pv = &fsu[offV + (nt * 8 + g) * VS_S + kb + tg];
                uint32_t bb[2] = {pv[0], pv[4]};
                mma_tf32(O[nt], a, bb);
            }
        }
    }

    // ---- Write output (tf32-rounded: feeds the O-projection GEMM) ----
    const float inv0 = 1.f / l[0];
    const float inv1 = 1.f / l[1];
    const int row0 = q0 + wband + g;
    float* base0 = ctx + (((size_t)b * Sq + row0) * HQn + h) * Dh;
    float* base1 = base0 + (size_t)8 * HQn * Dh;
#pragma unroll
    for (int nt = 0; nt < 16; nt++) {
        const int col = nt * 8 + tg * 2;
        *(float2*)&base0[col] = make_float2(roundtf(O[nt][0] * inv0),
                                            roundtf(O[nt][1] * inv0));
        *(float2*)&base1[col] = make_float2(roundtf(O[nt][2] * inv1),
                                            roundtf(O[nt][3] * inv1));
    }
}

// ---------------------------------------------------------------------------
// Launch
// ---------------------------------------------------------------------------
extern "C" void kernel_launch(void* const* d_in, const int* in_sizes, int n_in,
                              void* d_out, int out_size) {
    const float* hidden = (const float*)d_in[0];
    const float* cosb   = (const float*)d_in[1];
    const float* sinb   = (const float*)d_in[2];
    const float* Wq = (const float*)d_in[4];
    const float* Wk = (const float*)d_in[5];
    const float* Wv = (const float*)d_in[6];
    const float* Wo = (const float*)d_in[7];
    const float* qw = (const float*)d_in[8];
    const float* kw = (const float*)d_in[9];
    float* out = (float*)d_out;

    float *qb, *kb, *vb, *cb, *hidR, *wqkvT, *woT, *vtb;
    cudaGetSymbolAddress((void**)&qb, g_q);
    cudaGetSymbolAddress((void**)&kb, g_k);
    cudaGetSymbolAddress((void**)&vb, g_v);
    cudaGetSymbolAddress((void**)&cb, g_ctx);
    cudaGetSymbolAddress((void**)&hidR, g_hidR);
    cudaGetSymbolAddress((void**)&wqkvT, g_WqkvT);
    cudaGetSymbolAddress((void**)&woT, g_WoT);
    cudaGetSymbolAddress((void**)&vtb, g_vT);

    const int M = Bq * Sq;  // 4096
    const float scale = 0.088388347648318447f;  // 1/sqrt(128)

    // Pre-round hidden states to tf32 (rna)
    round_kernel<<<(M * Hd / 4 + 255) / 256, 256>>>(
        (const float4*)hidden, (float4*)hidR, M * Hd / 4);

    // Weight transposes + rounding
    transpose_kernel<<<dim3(64, 64), dim3(32, 8)>>>(Wq, wqkvT, 2048, 2048);
    transpose_kernel<<<dim3(16, 64), dim3(32, 8)>>>(
        Wk, wqkvT + (size_t)2048 * 2048, 2048, 512);
    transpose_kernel<<<dim3(16, 64), dim3(32, 8)>>>(
        Wv, wqkvT + (size_t)2560 * 2048, 2048, 512);
    transpose_kernel<<<dim3(64, 64), dim3(32, 8)>>>(Wo, woT, 2048, 2048);

    cudaFuncSetAttribute(gemm_async<1>,
                         cudaFuncAttributeMaxDynamicSharedMemorySize, GEMM_SMEM);
    cudaFuncSetAttribute(gemm_async<0>,
                         cudaFuncAttributeMaxDynamicSharedMemorySize, GEMM_SMEM);

    // Fused QKV projection
    gemm_async<1><<<dim3(24, 32), 256, GEMM_SMEM>>>(
        hidR, wqkvT, Hd, qb, kb, vb);

    // RMSNorm + RoPE (q pre-scaled by 1/sqrt(d); both tf32-rounded)
    rmsnorm_rope_kernel<<<Bq * Sq * HQn, Dh>>>(qb, qw, cosb, sinb, HQn, scale);
    rmsnorm_rope_kernel<<<Bq * Sq * HKVn, Dh>>>(kb, kw, cosb, sinb, HKVn, 1.0f);

    // V transpose + round
    vtrans_kernel<<<dim3(4, 64, Bq * HKVn), dim3(32, 8)>>>(vb, vtb);

    // Flash attention
    cudaFuncSetAttribute(flash_mma_kernel,
                         cudaFuncAttributeMaxDynamicSharedMemorySize, FLASH_SMEM);
    flash_mma_kernel<<<dim3(Sq / FBQ, Bq * HQn), 256, FLASH_SMEM>>>(
        qb, kb, vtb, cb);

    // Output projection
    gemm_async<0><<<dim3(16, 32), 256, GEMM_SMEM>>>(
        cb, woT, HQn * Dh, out, nullptr, nullptr);
}

// round 7
// speedup vs baseline: 7.2144x; 1.7540x over previous
#include <cuda_runtime.h>
#include <cuda_fp16.h>
#include <cstdint>

// Problem constants (fixed by the dataset)
#define Bq   2
#define Sq   2048
#define Hd   2048
#define HQn  16
#define HKVn 4
#define Dh   128
#define NREP (HQn / HKVn)

// Scratch (device globals; no runtime allocation allowed) — fp16 dataflow
__device__ __half g_qH[(size_t)Bq * Sq * HQn * Dh];     // 16 MB
__device__ __half g_kH[(size_t)Bq * Sq * HKVn * Dh];    // 4 MB
__device__ __half g_vH[(size_t)Bq * Sq * HKVn * Dh];    // 4 MB
__device__ __half g_ctxH[(size_t)Bq * Sq * HQn * Dh];   // 16 MB
__device__ __half g_hidH[(size_t)Bq * Sq * Hd];         // 16 MB
__device__ __half g_WqkvT[(size_t)3072 * 2048];         // 12 MB
__device__ __half g_WoT[(size_t)2048 * 2048];           // 8 MB
__device__ __half g_vT[(size_t)Bq * HKVn * Dh * Sq];    // 4 MB

// ---------------------------------------------------------------------------
// Helpers
// ---------------------------------------------------------------------------
__device__ __forceinline__ uint32_t smem_to_u32(const void* p) {
    uint32_t a;
    asm("{ .reg .u64 t; cvta.to.shared.u64 t, %1; cvt.u32.u64 %0, t; }"
        : "=r"(a) : "l"(p));
    return a;
}

__device__ __forceinline__ void mma_f16(float* d, const uint32_t* a,
                                        const uint32_t* b) {
    asm volatile(
        "mma.sync.aligned.m16n8k16.row.col.f32.f16.f16.f32 "
        "{%0,%1,%2,%3}, {%4,%5,%6,%7}, {%8,%9}, {%0,%1,%2,%3};"
        : "+f"(d[0]), "+f"(d[1]), "+f"(d[2]), "+f"(d[3])
        : "r"(a[0]), "r"(a[1]), "r"(a[2]), "r"(a[3]), "r"(b[0]), "r"(b[1]));
}

__device__ __forceinline__ void cpa16(uint32_t dst, const void* src) {
    asm volatile("cp.async.cg.shared.global [%0], [%1], 16;"
                 :: "r"(dst), "l"(src) : "memory");
}
#define CP_COMMIT() asm volatile("cp.async.commit_group;" ::: "memory")
#define CP_WAIT0()  asm volatile("cp.async.wait_group 0;" ::: "memory")
#define CP_WAIT1()  asm volatile("cp.async.wait_group 1;" ::: "memory")

// exp(x) for x <= 0 via FFMA-pipe exp2 polynomial (rel err <1e-5).
__device__ __forceinline__ float fexp(float x) {
    float t  = fmaxf(x, -87.0f) * 1.4426950408889634f;
    float fl = floorf(t);
    float f  = t - fl;
    float p  = 1.5403531e-4f;
    p = fmaf(p, f, 1.3333558e-3f);
    p = fmaf(p, f, 9.6181291e-3f);
    p = fmaf(p, f, 5.5504108e-2f);
    p = fmaf(p, f, 2.4022650e-1f);
    p = fmaf(p, f, 6.9314718e-1f);
    p = fmaf(p, f, 1.0f);
    int e = (int)fl;
    return __int_as_float((uint32_t)(e + 127) << 23) * p;
}

// ---------------------------------------------------------------------------
// fp32 -> fp16 conversion (hidden states)
// ---------------------------------------------------------------------------
__global__ void cvt_half_kernel(const float4* __restrict__ in,
                                __half2* __restrict__ out, int n4) {
    const int i = blockIdx.x * blockDim.x + threadIdx.x;
    if (i < n4) {
        float4 x = in[i];
        out[2 * i]     = __floats2half2_rn(x.x, x.y);
        out[2 * i + 1] = __floats2half2_rn(x.z, x.w);
    }
}

// ---------------------------------------------------------------------------
// Weight transpose + fp16 cvt: out[C][R] = h(in[R][C])
// ---------------------------------------------------------------------------
__global__ void transpose_kernel(const float* __restrict__ in,
                                 __half* __restrict__ out, int R, int C) {
    __shared__ float t[32][33];
    const int bx = blockIdx.x * 32, by = blockIdx.y * 32;
    const int x = threadIdx.x, y = threadIdx.y;
#pragma unroll
    for (int j = 0; j < 32; j += 8)
        t[y + j][x] = in[(size_t)(by + y + j) * C + bx + x];
    __syncthreads();
#pragma unroll
    for (int j = 0; j < 32; j += 8)
        out[(size_t)(bx + y + j) * R + by + x] = __float2half(t[x][y + j]);
}

// ---------------------------------------------------------------------------
// V transpose (fp16 in/out): vT[(b*4+hkv)][d][s]
// ---------------------------------------------------------------------------
__global__ void vtrans_kernel(const __half* __restrict__ v,
                              __half* __restrict__ vt) {
    __shared__ __half t[32][34];
    const int z = blockIdx.z;            // b*4 + hkv
    const int b = z >> 2, hkv = z & 3;
    const int s0 = blockIdx.y * 32, d0 = blockIdx.x * 32;
    const int x = threadIdx.x, y = threadIdx.y;
    const __half* src = v + (size_t)b * Sq * 512 + hkv * 128;
#pragma unroll
    for (int j = 0; j < 32; j += 8)
        t[y + j][x] = src[(size_t)(s0 + y + j) * 512 + d0 + x];
    __syncthreads();
    __half* dst = vt + ((size_t)z * 128 + d0) * Sq + s0;
#pragma unroll
    for (int j = 0; j < 32; j += 8)
        dst[(size_t)(y + j) * Sq + x] = t[x][y + j];
}

// ---------------------------------------------------------------------------
// FP16 m16n8k16 GEMM with cp.async 3-stage pipeline.
// CTA tile 128x128, BK=32 (2 k16-steps), 8 warps (2x4), warp tile 64x32.
// Word-level smem layout: 20 words (40 halves) per row, conflict-free frags.
// ---------------------------------------------------------------------------
#define NST  3
#define STW  2560                              // words per stage per operand
#define GEMM_SMEM (NST * STW * 2 * 4)          // 61440 B

template <int QKV, typename CT>
__global__ void __launch_bounds__(256, 2)
gemm_f16(const __half* __restrict__ A, const __half* __restrict__ Bt, int K,
         CT* __restrict__ C0, CT* __restrict__ C1, CT* __restrict__ C2) {
    extern __shared__ uint32_t smw[];
    const uint32_t smu = smem_to_u32(smw);

    const int tid = threadIdx.x;
    const int lane = tid & 31, wid = tid >> 5;
    const int wm = (wid & 1) * 64, wn = (wid >> 1) * 32;
    const int g = lane >> 2, tg = lane & 3;

    const int m0 = blockIdx.y * 128, n0 = blockIdx.x * 128;
    const __half* Ab = A + (size_t)m0 * K;
    const __half* Bb = Bt + (size_t)n0 * K;

    // Per-thread load coords: 512 16B-chunks per 128x32-half tile, 2/thread.
    const int r0 = tid >> 1;                // via f = tid + j*256: row = f>>2
    const int rowj[2] = {tid >> 2, (tid + 256) >> 2};
    const int c8 = (tid & 3) * 8;           // half offset within row
    (void)r0;

    const uint32_t stB = STW * 4;           // stage bytes
    uint32_t dA[2], dB[2];
#pragma unroll
    for (int j = 0; j < 2; j++) {
        dA[j] = smu + (uint32_t)(rowj[j] * 20 + c8 / 2) * 4;
        dB[j] = dA[j] + NST * stB;
    }

    const int nk = K / 32;

#pragma unroll
    for (int p = 0; p < NST - 1; p++) {
        const size_t kk = (size_t)p * 32 + c8;
#pragma unroll
        for (int j = 0; j < 2; j++) {
            cpa16(dA[j] + p * stB, Ab + (size_t)rowj[j] * K + kk);
            cpa16(dB[j] + p * stB, Bb + (size_t)rowj[j] * K + kk);
        }
        CP_COMMIT();
    }

    float acc[4][4][4];
#pragma unroll
    for (int mi = 0; mi < 4; mi++)
#pragma unroll
        for (int ni = 0; ni < 4; ni++)
#pragma unroll
            for (int e = 0; e < 4; e++) acc[mi][ni][e] = 0.f;

    for (int kt = 0; kt < nk; kt++) {
        CP_WAIT1();
        __syncthreads();

        const int kf = kt + NST - 1;
        if (kf < nk) {
            const int s = kf % NST;
            const size_t kk = (size_t)kf * 32 + c8;
#pragma unroll
            for (int j = 0; j < 2; j++) {
                cpa16(dA[j] + s * stB, Ab + (size_t)rowj[j] * K + kk);
                cpa16(dB[j] + s * stB, Bb + (size_t)rowj[j] * K + kk);
            }
        }
        CP_COMMIT();

        const uint32_t* aw = smw + (kt % NST) * STW;
        const uint32_t* bw = smw + NST * STW + (kt % NST) * STW;
#pragma unroll
        for (int ks = 0; ks < 2; ks++) {
            const int kb = ks * 8;          // word offset of this k16 step
            uint32_t af[4][4], bf[4][2];
#pragma unroll
            for (int mi = 0; mi < 4; mi++) {
                const uint32_t* p = &aw[(wm + mi * 16 + g) * 20 + kb + tg];
                af[mi][0] = p[0];
                af[mi][1] = p[8 * 20];
                af[mi][2] = p[4];
                af[mi][3] = p[8 * 20 + 4];
            }
#pragma unroll
            for (int ni = 0; ni < 4; ni++) {
                const uint32_t* p = &bw[(wn + ni * 8 + g) * 20 + kb + tg];
                bf[ni][0] = p[0];
                bf[ni][1] = p[4];
            }
#pragma unroll
            for (int mi = 0; mi < 4; mi++)
#pragma unroll
                for (int ni = 0; ni < 4; ni++)
                    mma_f16(acc[mi][ni], af[mi], bf[ni]);
        }
    }

    // Epilogue with output routing
    CT* C;
    int ldc, col0;
    if (QKV) {
        if (n0 < 2048)      { C = C0; ldc = 2048; col0 = n0; }
        else if (n0 < 2560) { C = C1; ldc = 512;  col0 = n0 - 2048; }
        else                { C = C2; ldc = 512;  col0 = n0 - 2560; }
    } else {
        C = C0; ldc = 2048; col0 = n0;
    }
#pragma unroll
    for (int mi = 0; mi < 4; mi++) {
        const int row0 = m0 + wm + mi * 16 + g;
#pragma unroll
        for (int ni = 0; ni < 4; ni++) {
            const int col = col0 + wn + ni * 8 + tg * 2;
            if constexpr (sizeof(CT) == 2) {
                *(__half2*)&C[(size_t)row0 * ldc + col] =
                    __floats2half2_rn(acc[mi][ni][0], acc[mi][ni][1]);
                *(__half2*)&C[(size_t)(row0 + 8) * ldc + col] =
                    __floats2half2_rn(acc[mi][ni][2], acc[mi][ni][3]);
            } else {
                *(float2*)&C[(size_t)row0 * ldc + col] =
                    make_float2(acc[mi][ni][0], acc[mi][ni][1]);
                *(float2*)&C[(size_t)(row0 + 8) * ldc + col] =
                    make_float2(acc[mi][ni][2], acc[mi][ni][3]);
            }
        }
    }
}

// ---------------------------------------------------------------------------
// Fused RMSNorm + RoPE (fp16 in/out, fp32 math); scaled by outscale.
// ---------------------------------------------------------------------------
__global__ void rmsnorm_rope_kernel(__half* __restrict__ x,
                                    const float* __restrict__ w,
                                    const float* __restrict__ cosb,
                                    const float* __restrict__ sinb,
                                    int nheads, float outscale) {
    const int idx = blockIdx.x;
    const int s   = (idx / nheads) % Sq;
    const int d   = threadIdx.x;
    __half* row   = x + (size_t)idx * Dh;

    float v  = __half2float(row[d]);
    float ss = v * v;
#pragma unroll
    for (int off = 16; off > 0; off >>= 1)
        ss += __shfl_xor_sync(0xffffffffu, ss, off);

    __shared__ float red[4];
    if ((d & 31) == 0) red[d >> 5] = ss;
    __syncthreads();
    float tot  = red[0] + red[1] + red[2] + red[3];
    float rinv = rsqrtf(tot / Dh + 1e-6f);
    float xn   = v * rinv * w[d];

    __shared__ float smv[Dh];
    smv[d] = xn;
    __syncthreads();
    float rot = (d < Dh / 2) ? -smv[d + Dh / 2] : smv[d - Dh / 2];
    float c   = cosb[(size_t)s * Dh + d];
    float sn  = sinb[(size_t)s * Dh + d];
    row[d]    = __float2half((xn * c + rot * sn) * outscale);
}

// ---------------------------------------------------------------------------
// Flash attention, fp16 m16n8k16 mma, double-buffered K/V via cp.async.
// BQ=128 (8 warps x 16 rows), BKV=64. Word strides: Q/K 68, V/P 36.
// P has its own region (fp16 halved smem) -> single __syncthreads per tile.
// ---------------------------------------------------------------------------
#define FBQ   128
#define FBKV  64
#define QW_S  68                      // words per Q/K row (128 halves + pad)
#define VW_S  36                      // words per V^T/P row (64 halves + pad)
#define OFFW_Q  0
#define OFFW_K0 (FBQ * QW_S)          // 8704
#define KW_STG  (FBKV * QW_S)         // 4352
#define OFFW_V0 (OFFW_K0 + 2 * KW_STG)        // 17408
#define VW_STG  (Dh * VW_S)           // 4608
#define OFFW_P  (OFFW_V0 + 2 * VW_STG)        // 26624
#define FLASH_SMEM ((OFFW_P + FBQ * VW_S) * 4)   // 124928 B

__global__ void __launch_bounds__(256, 1)
flash_mma_kernel(const __half* __restrict__ q,
                 const __half* __restrict__ k,
                 const __half* __restrict__ vt,
                 __half* __restrict__ ctx) {
    extern __shared__ uint32_t fsw[];
    const uint32_t fsb = smem_to_u32(fsw);

    const int bh  = blockIdx.y;
    const int b   = bh / HQn;
    const int h   = bh % HQn;
    const int hkv = h / NREP;
    const int q0  = (gridDim.x - 1 - blockIdx.x) * FBQ;

    const int tid  = threadIdx.x;
    const int lane = tid & 31, wid = tid >> 5;
    const int g = lane >> 2, tg = lane & 3;
    const int wband = wid * 16;

    const __half* kbase = k + ((size_t)b * Sq * HKVn + hkv) * Dh;
    const __half* vbase = vt + (size_t)(b * HKVn + hkv) * Dh * Sq;

    // Prologue: Q tile + KV tile 0, one commit group.
    const __half* qbase = q + (((size_t)b * Sq + q0) * HQn + h) * Dh;
#pragma unroll
    for (int j = 0; j < 8; j++) {       // Q: 128x128 halves, 8 chunks/thread
        const int f = tid + j * 256;
        const int r = f >> 4, c4w = (f & 15) * 4;
        cpa16(fsb + (uint32_t)(OFFW_Q + r * QW_S + c4w) * 4,
              qbase + (size_t)r * HQn * Dh + c4w * 2);
    }
#pragma unroll
    for (int j = 0; j < 4; j++) {       // K: 64x128, V: 128x64
        const int f = tid + j * 256;
        const int rk = f >> 4, ckw = (f & 15) * 4;
        cpa16(fsb + (uint32_t)(OFFW_K0 + rk * QW_S + ckw) * 4,
              kbase + (size_t)rk * HKVn * Dh + ckw * 2);
        const int rv = f >> 3, cvw = (f & 7) * 4;
        cpa16(fsb + (uint32_t)(OFFW_V0 + rv * VW_S + cvw) * 4,
              vbase + (size_t)rv * Sq + cvw * 2);
    }
    CP_COMMIT();

    float m[2], l[2], O[16][4];
    m[0] = m[1] = -1e30f;
    l[0] = l[1] = 0.f;
#pragma unroll
    for (int nt = 0; nt < 16; nt++)
#pragma unroll
        for (int e = 0; e < 4; e++) O[nt][e] = 0.f;

    const int ntile = (q0 + FBQ) / FBKV;
    for (int i = 0; i < ntile; i++) {
        const int st = i & 1;
        const int offK = OFFW_K0 + st * KW_STG;
        const int offV = OFFW_V0 + st * VW_STG;

        CP_WAIT0();          // KV[i] (+Q on i=0) arrived
        __syncthreads();     // prev tile's reads of the other stage are done

        if (i + 1 < ntile) { // prefetch KV[i+1] into the other stage
            const int k0n = (i + 1) * FBKV;
            const int offKn = OFFW_K0 + (st ^ 1) * KW_STG;
            const int offVn = OFFW_V0 + (st ^ 1) * VW_STG;
#pragma unroll
            for (int j = 0; j < 4; j++) {
                const int f = tid + j * 256;
                const int rk = f >> 4, ckw = (f & 15) * 4;
                cpa16(fsb + (uint32_t)(offKn + rk * QW_S + ckw) * 4,
                      kbase + (size_t)(k0n + rk) * HKVn * Dh + ckw * 2);
                const int rv = f >> 3, cvw = (f & 7) * 4;
                cpa16(fsb + (uint32_t)(offVn + rv * VW_S + cvw) * 4,
                      vbase + (size_t)rv * Sq + k0n + cvw * 2);
            }
        }
        CP_COMMIT();

        // ---- Scores: 8 k16-steps over Dh=128 ----
        float sc[8][4];
#pragma unroll
        for (int nt = 0; nt < 8; nt++)
#pragma unroll
            for (int e = 0; e < 4; e++) sc[nt][e] = 0.f;

#pragma unroll
        for (int ks = 0; ks < 8; ks++) {
            const int kb = ks * 8;          // word offset
            uint32_t a[4];
            {
                const uint32_t* p = &fsw[OFFW_Q + (wband + g) * QW_S + kb + tg];
                a[0] = p[0];
                a[1] = p[8 * QW_S];
                a[2] = p[4];
                a[3] = p[8 * QW_S + 4];
            }
#pragma unroll
            for (int nt = 0; nt < 8; nt++) {
                const uint32_t* pk = &fsw[offK + (nt * 8 + g) * QW_S + kb + tg];
                uint32_t bb[2] = {pk[0], pk[4]};
                mma_f16(sc[nt], a, bb);
            }
        }

        // Causal mask (tiles intersecting the diagonal)
        const int k0 = i * FBKV;
        if (k0 + FBKV - 1 > q0) {
#pragma unroll
            for (int nt = 0; nt < 8; nt++)
#pragma unroll
                for (int e = 0; e < 4; e++) {
                    const int qg = q0 + wband + g + ((e >> 1) << 3);
                    const int kg = k0 + nt * 8 + tg * 2 + (e & 1);
                    if (kg > qg) sc[nt][e] = -1e30f;
                }
        }

        // ---- Online softmax (rows g and g+8; 4 lanes share each row) ----
        float corr[2];
#pragma unroll
        for (int r2 = 0; r2 < 2; r2++) {
            float tm = -1e30f;
#pragma unroll
            for (int nt = 0; nt < 8; nt++)
                tm = fmaxf(tm, fmaxf(sc[nt][r2 * 2], sc[nt][r2 * 2 + 1]));
            tm = fmaxf(tm, __shfl_xor_sync(0xffffffffu, tm, 1));
            tm = fmaxf(tm, __shfl_xor_sync(0xffffffffu, tm, 2));
            const float mn = fmaxf(m[r2], tm);
            corr[r2] = fexp(m[r2] - mn);
            m[r2] = mn;
            float s2 = 0.f;
            const int prow = OFFW_P + (wband + g + r2 * 8) * VW_S;
#pragma unroll
            for (int nt = 0; nt < 8; nt++) {
                float p0 = fexp(sc[nt][r2 * 2]     - mn);
                float p1 = fexp(sc[nt][r2 * 2 + 1] - mn);
                __half2 hp = __floats2half2_rn(p0, p1);
                float2 pr = __half22float2(hp);   // sum the ROUNDED values
                s2 += pr.x + pr.y;
                fsw[prow + nt * 4 + tg] = *(uint32_t*)&hp;
            }
            s2 += __shfl_xor_sync(0xffffffffu, s2, 1);
            s2 += __shfl_xor_sync(0xffffffffu, s2, 2);
            l[r2] = l[r2] * corr[r2] + s2;
        }

#pragma unroll
        for (int nt = 0; nt < 16; nt++) {
            O[nt][0] *= corr[0]; O[nt][1] *= corr[0];
            O[nt][2] *= corr[1]; O[nt][3] *= corr[1];
        }
        __syncwarp();   // own-warp P rows visible to own warp

        // ---- PV: 4 k16-steps over BKV=64 ----
#pragma unroll
        for (int ks = 0; ks < 4; ks++) {
            const int kb = ks * 8;
            uint32_t a[4];
            {
                const uint32_t* p = &fsw[OFFW_P + (wband + g) * VW_S + kb + tg];
                a[0] = p[0];
                a[1] = p[8 * VW_S];
                a[2] = p[4];
                a[3] = p[8 * VW_S + 4];
            }
#pragma unroll
            for (int nt = 0; nt < 16; nt++) {
                const uint32_t* pv = &fsw[offV + (nt * 8 + g) * VW_S + kb + tg];
                uint32_t bb[2] = {pv[0], pv[4]};
                mma_f16(O[nt], a, bb);
            }
        }
    }

    // ---- Write output as fp16 (feeds the O-projection GEMM) ----
    const float inv0 = 1.f / l[0];
    const float inv1 = 1.f / l[1];
    const int row0 = q0 + wband + g;
    __half* base0 = ctx + (((size_t)b * Sq + row0) * HQn + h) * Dh;
    __half* base1 = base0 + (size_t)8 * HQn * Dh;
#pragma unroll
    for (int nt = 0; nt < 16; nt++) {
        const int col = nt * 8 + tg * 2;
        *(__half2*)&base0[col] = __floats2half2_rn(O[nt][0] * inv0,
                                                   O[nt][1] * inv0);
        *(__half2*)&base1[col] = __floats2half2_rn(O[nt][2] * inv1,
                                                   O[nt][3] * inv1);
    }
}

// ---------------------------------------------------------------------------
// Launch
// ---------------------------------------------------------------------------
extern "C" void kernel_launch(void* const* d_in, const int* in_sizes, int n_in,
                              void* d_out, int out_size) {
    const float* hidden = (const float*)d_in[0];
    const float* cosb   = (const float*)d_in[1];
    const float* sinb   = (const float*)d_in[2];
    const float* Wq = (const float*)d_in[4];
    const float* Wk = (const float*)d_in[5];
    const float* Wv = (const float*)d_in[6];
    const float* Wo = (const float*)d_in[7];
    const float* qw = (const float*)d_in[8];
    const float* kw = (const float*)d_in[9];
    float* out = (float*)d_out;

    __half *qb, *kb, *vb, *cb, *hidH, *wqkvT, *woT, *vtb;
    cudaGetSymbolAddress((void**)&qb, g_qH);
    cudaGetSymbolAddress((void**)&kb, g_kH);
    cudaGetSymbolAddress((void**)&vb, g_vH);
    cudaGetSymbolAddress((void**)&cb, g_ctxH);
    cudaGetSymbolAddress((void**)&hidH, g_hidH);
    cudaGetSymbolAddress((void**)&wqkvT, g_WqkvT);
    cudaGetSymbolAddress((void**)&woT, g_WoT);
    cudaGetSymbolAddress((void**)&vtb, g_vT);

    const int M = Bq * Sq;  // 4096
    const float scale = 0.088388347648318447f;  // 1/sqrt(128)

    // Convert hidden states to fp16
    cvt_half_kernel<<<(M * Hd / 4 + 255) / 256, 256>>>(
        (const float4*)hidden, (__half2*)hidH, M * Hd / 4);

    // Weight transposes + fp16 cvt
    transpose_kernel<<<dim3(64, 64), dim3(32, 8)>>>(Wq, wqkvT, 2048, 2048);
    transpose_kernel<<<dim3(16, 64), dim3(32, 8)>>>(
        Wk, wqkvT + (size_t)2048 * 2048, 2048, 512);
    transpose_kernel<<<dim3(16, 64), dim3(32, 8)>>>(
        Wv, wqkvT + (size_t)2560 * 2048, 2048, 512);
    transpose_kernel<<<dim3(64, 64), dim3(32, 8)>>>(Wo, woT, 2048, 2048);

    cudaFuncSetAttribute((const void*)gemm_f16<1, __half>,
                         cudaFuncAttributeMaxDynamicSharedMemorySize, GEMM_SMEM);
    cudaFuncSetAttribute((const void*)gemm_f16<0, float>,
                         cudaFuncAttributeMaxDynamicSharedMemorySize, GEMM_SMEM);

    // Fused QKV projection (fp16 out)
    gemm_f16<1, __half><<<dim3(24, 32), 256, GEMM_SMEM>>>(
        hidH, wqkvT, Hd, qb, kb, vb);

    // RMSNorm + RoPE (q pre-scaled by 1/sqrt(d))
    rmsnorm_rope_kernel<<<Bq * Sq * HQn, Dh>>>(qb, qw, cosb, sinb, HQn, scale);
    rmsnorm_rope_kernel<<<Bq * Sq * HKVn, Dh>>>(kb, kw, cosb, sinb, HKVn, 1.0f);

    // V transpose
    vtrans_kernel<<<dim3(4, 64, Bq * HKVn), dim3(32, 8)>>>(vb, vtb);

    // Flash attention
    cudaFuncSetAttribute(flash_mma_kernel,
                         cudaFuncAttributeMaxDynamicSharedMemorySize, FLASH_SMEM);
    flash_mma_kernel<<<dim3(Sq / FBQ, Bq * HQn), 256, FLASH_SMEM>>>(
        qb, kb, vtb, cb);

    // Output projection (fp32 out)
    gemm_f16<0, float><<<dim3(16, 32), 256, GEMM_SMEM>>>(
        cb, woT, HQn * Dh, out, nullptr, nullptr);
}

// round 8
// speedup vs baseline: 7.8986x; 1.0948x over previous
#include <cuda_runtime.h>
#include <cuda_fp16.h>
#include <cstdint>

// Problem constants (fixed by the dataset)
#define Bq   2
#define Sq   2048
#define Hd   2048
#define HQn  16
#define HKVn 4
#define Dh   128
#define NREP (HQn / HKVn)

// Scratch (device globals; no runtime allocation allowed) — fp16 dataflow
__device__ __half g_qH[(size_t)Bq * Sq * HQn * Dh];     // 16 MB
__device__ __half g_kH[(size_t)Bq * Sq * HKVn * Dh];    // 4 MB
__device__ __half g_vH[(size_t)Bq * Sq * HKVn * Dh];    // 4 MB
__device__ __half g_ctxH[(size_t)Bq * Sq * HQn * Dh];   // 16 MB
__device__ __half g_hidH[(size_t)Bq * Sq * Hd];         // 16 MB
__device__ __half g_WqkvT[(size_t)3072 * 2048];         // 12 MB
__device__ __half g_WoT[(size_t)2048 * 2048];           // 8 MB
__device__ __half g_vT[(size_t)Bq * HKVn * Dh * Sq];    // 4 MB

// ---------------------------------------------------------------------------
// Helpers
// ---------------------------------------------------------------------------
__device__ __forceinline__ uint32_t smem_to_u32(const void* p) {
    uint32_t a;
    asm("{ .reg .u64 t; cvta.to.shared.u64 t, %1; cvt.u32.u64 %0, t; }"
        : "=r"(a) : "l"(p));
    return a;
}

__device__ __forceinline__ void mma_f16(float* d, const uint32_t* a,
                                        const uint32_t* b) {
    asm volatile(
        "mma.sync.aligned.m16n8k16.row.col.f32.f16.f16.f32 "
        "{%0,%1,%2,%3}, {%4,%5,%6,%7}, {%8,%9}, {%0,%1,%2,%3};"
        : "+f"(d[0]), "+f"(d[1]), "+f"(d[2]), "+f"(d[3])
        : "r"(a[0]), "r"(a[1]), "r"(a[2]), "r"(a[3]), "r"(b[0]), "r"(b[1]));
}

__device__ __forceinline__ void cpa16(uint32_t dst, const void* src) {
    asm volatile("cp.async.cg.shared.global [%0], [%1], 16;"
                 :: "r"(dst), "l"(src) : "memory");
}
#define CP_COMMIT() asm volatile("cp.async.commit_group;" ::: "memory")
#define CP_WAIT0()  asm volatile("cp.async.wait_group 0;" ::: "memory")
#define CP_WAIT1()  asm volatile("cp.async.wait_group 1;" ::: "memory")

// exp(x) for x <= 0 via FFMA-pipe exp2 polynomial (rel err <1e-5).
__device__ __forceinline__ float fexp(float x) {
    float t  = fmaxf(x, -87.0f) * 1.4426950408889634f;
    float fl = floorf(t);
    float f  = t - fl;
    float p  = 1.5403531e-4f;
    p = fmaf(p, f, 1.3333558e-3f);
    p = fmaf(p, f, 9.6181291e-3f);
    p = fmaf(p, f, 5.5504108e-2f);
    p = fmaf(p, f, 2.4022650e-1f);
    p = fmaf(p, f, 6.9314718e-1f);
    p = fmaf(p, f, 1.0f);
    int e = (int)fl;
    return __int_as_float((uint32_t)(e + 127) << 23) * p;
}

// ---------------------------------------------------------------------------
// fp32 -> fp16 conversion (hidden states)
// ---------------------------------------------------------------------------
__global__ void cvt_half_kernel(const float4* __restrict__ in,
                                __half2* __restrict__ out, int n4) {
    const int i = blockIdx.x * blockDim.x + threadIdx.x;
    if (i < n4) {
        float4 x = in[i];
        out[2 * i]     = __floats2half2_rn(x.x, x.y);
        out[2 * i + 1] = __floats2half2_rn(x.z, x.w);
    }
}

// ---------------------------------------------------------------------------
// All four weight transposes in one launch (blockIdx.z routes).
// out[C][R] = h(in[R][C]).  z=0: Wq, z=1: Wk, z=2: Wv, z=3: Wo.
// ---------------------------------------------------------------------------
__global__ void transpose_all_kernel(const float* __restrict__ Wq,
                                     const float* __restrict__ Wk,
                                     const float* __restrict__ Wv,
                                     const float* __restrict__ Wo,
                                     __half* __restrict__ wqkvT,
                                     __half* __restrict__ woT) {
    const int z = blockIdx.z;
    const float* in;
    __half* out;
    int C;   // input cols (R is always 2048)
    if (z == 0)      { in = Wq; out = wqkvT;                         C = 2048; }
    else if (z == 1) { in = Wk; out = wqkvT + (size_t)2048 * 2048;   C = 512; }
    else if (z == 2) { in = Wv; out = wqkvT + (size_t)2560 * 2048;   C = 512; }
    else             { in = Wo; out = woT;                           C = 2048; }
    const int bx = blockIdx.x * 32, by = blockIdx.y * 32;
    if (bx >= C) return;

    __shared__ float t[32][33];
    const int x = threadIdx.x, y = threadIdx.y;
#pragma unroll
    for (int j = 0; j < 32; j += 8)
        t[y + j][x] = in[(size_t)(by + y + j) * C + bx + x];
    __syncthreads();
#pragma unroll
    for (int j = 0; j < 32; j += 8)
        out[(size_t)(bx + y + j) * 2048 + by + x] = __float2half(t[x][y + j]);
}

// ---------------------------------------------------------------------------
// V transpose (fp16 in/out): vT[(b*4+hkv)][d][s]
// ---------------------------------------------------------------------------
__global__ void vtrans_kernel(const __half* __restrict__ v,
                              __half* __restrict__ vt) {
    __shared__ __half t[32][34];
    const int z = blockIdx.z;            // b*4 + hkv
    const int b = z >> 2, hkv = z & 3;
    const int s0 = blockIdx.y * 32, d0 = blockIdx.x * 32;
    const int x = threadIdx.x, y = threadIdx.y;
    const __half* src = v + (size_t)b * Sq * 512 + hkv * 128;
#pragma unroll
    for (int j = 0; j < 32; j += 8)
        t[y + j][x] = src[(size_t)(s0 + y + j) * 512 + d0 + x];
    __syncthreads();
    __half* dst = vt + ((size_t)z * 128 + d0) * Sq + s0;
#pragma unroll
    for (int j = 0; j < 32; j += 8)
        dst[(size_t)(y + j) * Sq + x] = t[x][y + j];
}

// ---------------------------------------------------------------------------
// FP16 m16n8k16 GEMM with cp.async 3-stage pipeline (round-7, passing).
// ---------------------------------------------------------------------------
#define NST  3
#define STW  2560
#define GEMM_SMEM (NST * STW * 2 * 4)          // 61440 B

template <int QKV, typename CT>
__global__ void __launch_bounds__(256, 2)
gemm_f16(const __half* __restrict__ A, const __half* __restrict__ Bt, int K,
         CT* __restrict__ C0, CT* __restrict__ C1, CT* __restrict__ C2) {
    extern __shared__ uint32_t smw[];
    const uint32_t smu = smem_to_u32(smw);

    const int tid = threadIdx.x;
    const int lane = tid & 31, wid = tid >> 5;
    const int wm = (wid & 1) * 64, wn = (wid >> 1) * 32;
    const int g = lane >> 2, tg = lane & 3;

    const int m0 = blockIdx.y * 128, n0 = blockIdx.x * 128;
    const __half* Ab = A + (size_t)m0 * K;
    const __half* Bb = Bt + (size_t)n0 * K;

    const int rowj[2] = {tid >> 2, (tid + 256) >> 2};
    const int c8 = (tid & 3) * 8;

    const uint32_t stB = STW * 4;
    uint32_t dA[2], dB[2];
#pragma unroll
    for (int j = 0; j < 2; j++) {
        dA[j] = smu + (uint32_t)(rowj[j] * 20 + c8 / 2) * 4;
        dB[j] = dA[j] + NST * stB;
    }

    const int nk = K / 32;

#pragma unroll
    for (int p = 0; p < NST - 1; p++) {
        const size_t kk = (size_t)p * 32 + c8;
#pragma unroll
        for (int j = 0; j < 2; j++) {
            cpa16(dA[j] + p * stB, Ab + (size_t)rowj[j] * K + kk);
            cpa16(dB[j] + p * stB, Bb + (size_t)rowj[j] * K + kk);
        }
        CP_COMMIT();
    }

    float acc[4][4][4];
#pragma unroll
    for (int mi = 0; mi < 4; mi++)
#pragma unroll
        for (int ni = 0; ni < 4; ni++)
#pragma unroll
            for (int e = 0; e < 4; e++) acc[mi][ni][e] = 0.f;

    for (int kt = 0; kt < nk; kt++) {
        CP_WAIT1();
        __syncthreads();

        const int kf = kt + NST - 1;
        if (kf < nk) {
            const int s = kf % NST;
            const size_t kk = (size_t)kf * 32 + c8;
#pragma unroll
            for (int j = 0; j < 2; j++) {
                cpa16(dA[j] + s * stB, Ab + (size_t)rowj[j] * K + kk);
                cpa16(dB[j] + s * stB, Bb + (size_t)rowj[j] * K + kk);
            }
        }
        CP_COMMIT();

        const uint32_t* aw = smw + (kt % NST) * STW;
        const uint32_t* bw = smw + NST * STW + (kt % NST) * STW;
#pragma unroll
        for (int ks = 0; ks < 2; ks++) {
            const int kb = ks * 8;
            uint32_t af[4][4], bf[4][2];
#pragma unroll
            for (int mi = 0; mi < 4; mi++) {
                const uint32_t* p = &aw[(wm + mi * 16 + g) * 20 + kb + tg];
                af[mi][0] = p[0];
                af[mi][1] = p[8 * 20];
                af[mi][2] = p[4];
                af[mi][3] = p[8 * 20 + 4];
            }
#pragma unroll
            for (int ni = 0; ni < 4; ni++) {
                const uint32_t* p = &bw[(wn + ni * 8 + g) * 20 + kb + tg];
                bf[ni][0] = p[0];
                bf[ni][1] = p[4];
            }
#pragma unroll
            for (int mi = 0; mi < 4; mi++)
#pragma unroll
                for (int ni = 0; ni < 4; ni++)
                    mma_f16(acc[mi][ni], af[mi], bf[ni]);
        }
    }

    CT* C;
    int ldc, col0;
    if (QKV) {
        if (n0 < 2048)      { C = C0; ldc = 2048; col0 = n0; }
        else if (n0 < 2560) { C = C1; ldc = 512;  col0 = n0 - 2048; }
        else                { C = C2; ldc = 512;  col0 = n0 - 2560; }
    } else {
        C = C0; ldc = 2048; col0 = n0;
    }
#pragma unroll
    for (int mi = 0; mi < 4; mi++) {
        const int row0 = m0 + wm + mi * 16 + g;
#pragma unroll
        for (int ni = 0; ni < 4; ni++) {
            const int col = col0 + wn + ni * 8 + tg * 2;
            if constexpr (sizeof(CT) == 2) {
                *(__half2*)&C[(size_t)row0 * ldc + col] =
                    __floats2half2_rn(acc[mi][ni][0], acc[mi][ni][1]);
                *(__half2*)&C[(size_t)(row0 + 8) * ldc + col] =
                    __floats2half2_rn(acc[mi][ni][2], acc[mi][ni][3]);
            } else {
                *(float2*)&C[(size_t)row0 * ldc + col] =
                    make_float2(acc[mi][ni][0], acc[mi][ni][1]);
                *(float2*)&C[(size_t)(row0 + 8) * ldc + col] =
                    make_float2(acc[mi][ni][2], acc[mi][ni][3]);
            }
        }
    }
}

// ---------------------------------------------------------------------------
// Warp-per-row RMSNorm + RoPE, q and k in ONE launch.
// Each lane holds cols {2l, 2l+1} and {64+2l, 64+2l+1}: the rotate-half
// partner lives in-lane, so the whole row needs only warp shuffles.
// ---------------------------------------------------------------------------
#define NQROWS (Bq * Sq * HQn)       // 65536
#define NKROWS (Bq * Sq * HKVn)      // 16384

__global__ void rmsnorm_rope2_kernel(__half* __restrict__ qx,
                                     __half* __restrict__ kx,
                                     const float* __restrict__ qw,
                                     const float* __restrict__ kw,
                                     const float* __restrict__ cosb,
                                     const float* __restrict__ sinb,
                                     float qscale) {
    const int row = blockIdx.x * 8 + (threadIdx.x >> 5);
    const int l   = threadIdx.x & 31;

    __half* x;
    const float* w;
    float scale;
    int r, nheads;
    if (row < NQROWS) { x = qx; w = qw; scale = qscale; r = row; nheads = HQn; }
    else              { x = kx; w = kw; scale = 1.0f;  r = row - NQROWS; nheads = HKVn; }
    const int s = (r / nheads) % Sq;

    __half2* rp = (__half2*)(x + (size_t)r * Dh);
    float2 a = __half22float2(rp[l]);        // cols 2l, 2l+1
    float2 b = __half22float2(rp[l + 32]);   // cols 64+2l, 64+2l+1

    float ss = a.x * a.x + a.y * a.y + b.x * b.x + b.y * b.y;
#pragma unroll
    for (int off = 16; off > 0; off >>= 1)
        ss += __shfl_xor_sync(0xffffffffu, ss, off);
    const float rinv = rsqrtf(ss * (1.0f / Dh) + 1e-6f);

    const float2 wa = *(const float2*)&w[2 * l];
    const float2 wb = *(const float2*)&w[64 + 2 * l];
    const float xa0 = a.x * rinv * wa.x, xa1 = a.y * rinv * wa.y;
    const float xb0 = b.x * rinv * wb.x, xb1 = b.y * rinv * wb.y;

    const float* cb = cosb + (size_t)s * Dh;
    const float* sb = sinb + (size_t)s * Dh;
    const float2 ca = *(const float2*)&cb[2 * l];
    const float2 cb2 = *(const float2*)&cb[64 + 2 * l];
    const float2 sa = *(const float2*)&sb[2 * l];
    const float2 sb2 = *(const float2*)&sb[64 + 2 * l];

    // out[d]   = xn[d]*cos[d]   - xn[d+64]*sin[d]      (d < 64)
    // out[d64] = xn[d64]*cos[d64] + xn[d]*sin[d64]
    const float oa0 = (xa0 * ca.x - xb0 * sa.x) * scale;
    const float oa1 = (xa1 * ca.y - xb1 * sa.y) * scale;
    const float ob0 = (xb0 * cb2.x + xa0 * sb2.x) * scale;
    const float ob1 = (xb1 * cb2.y + xa1 * sb2.y) * scale;

    rp[l]      = __floats2half2_rn(oa0, oa1);
    rp[l + 32] = __floats2half2_rn(ob0, ob1);
}

// ---------------------------------------------------------------------------
// Flash attention, fp16 m16n8k16, FBQ=64 / 128 threads -> occupancy 2:
// one CTA's softmax overlaps the other's MMAs on the same SM.
// ---------------------------------------------------------------------------
#define FBQ   64
#define FBKV  64
#define QW_S  68
#define VW_S  36
#define OFFW_Q  0
#define OFFW_K0 (FBQ * QW_S)                  // 4352
#define KW_STG  (FBKV * QW_S)                 // 4352
#define OFFW_V0 (OFFW_K0 + 2 * KW_STG)        // 13056
#define VW_STG  (Dh * VW_S)                   // 4608
#define OFFW_P  (OFFW_V0 + 2 * VW_STG)        // 22272
#define FLASH_SMEM ((OFFW_P + FBQ * VW_S) * 4)   // 98304 B

__global__ void __launch_bounds__(128, 2)
flash_mma_kernel(const __half* __restrict__ q,
                 const __half* __restrict__ k,
                 const __half* __restrict__ vt,
                 __half* __restrict__ ctx) {
    extern __shared__ uint32_t fsw[];
    const uint32_t fsb = smem_to_u32(fsw);

    const int bh  = blockIdx.y;
    const int b   = bh / HQn;
    const int h   = bh % HQn;
    const int hkv = h / NREP;
    const int q0  = (gridDim.x - 1 - blockIdx.x) * FBQ;

    const int tid  = threadIdx.x;
    const int lane = tid & 31, wid = tid >> 5;   // 4 warps
    const int g = lane >> 2, tg = lane & 3;
    const int wband = wid * 16;

    const __half* kbase = k + ((size_t)b * Sq * HKVn + hkv) * Dh;
    const __half* vbase = vt + (size_t)(b * HKVn + hkv) * Dh * Sq;

    // Prologue: Q tile + KV tile 0, one commit group. (128-thread strides)
    const __half* qbase = q + (((size_t)b * Sq + q0) * HQn + h) * Dh;
#pragma unroll
    for (int j = 0; j < 8; j++) {
        const int f = tid + j * 128;
        const int r = f >> 4, c4w = (f & 15) * 4;
        cpa16(fsb + (uint32_t)(OFFW_Q + r * QW_S + c4w) * 4,
              qbase + (size_t)r * HQn * Dh + c4w * 2);
        cpa16(fsb + (uint32_t)(OFFW_K0 + r * QW_S + c4w) * 4,
              kbase + (size_t)r * HKVn * Dh + c4w * 2);
        const int rv = f >> 3, cvw = (f & 7) * 4;
        cpa16(fsb + (uint32_t)(OFFW_V0 + rv * VW_S + cvw) * 4,
              vbase + (size_t)rv * Sq + cvw * 2);
    }
    CP_COMMIT();

    float m[2], l[2], O[16][4];
    m[0] = m[1] = -1e30f;
    l[0] = l[1] = 0.f;
#pragma unroll
    for (int nt = 0; nt < 16; nt++)
#pragma unroll
        for (int e = 0; e < 4; e++) O[nt][e] = 0.f;

    const int ntile = (q0 + FBQ) / FBKV;
    for (int i = 0; i < ntile; i++) {
        const int st = i & 1;
        const int offK = OFFW_K0 + st * KW_STG;
        const int offV = OFFW_V0 + st * VW_STG;

        CP_WAIT0();
        __syncthreads();

        if (i + 1 < ntile) {
            const int k0n = (i + 1) * FBKV;
            const int offKn = OFFW_K0 + (st ^ 1) * KW_STG;
            const int offVn = OFFW_V0 + (st ^ 1) * VW_STG;
#pragma unroll
            for (int j = 0; j < 8; j++) {
                const int f = tid + j * 128;
                const int rk = f >> 4, ckw = (f & 15) * 4;
                cpa16(fsb + (uint32_t)(offKn + rk * QW_S + ckw) * 4,
                      kbase + (size_t)(k0n + rk) * HKVn * Dh + ckw * 2);
                const int rv = f >> 3, cvw = (f & 7) * 4;
                cpa16(fsb + (uint32_t)(offVn + rv * VW_S + cvw) * 4,
                      vbase + (size_t)rv * Sq + k0n + cvw * 2);
            }
        }
        CP_COMMIT();

        // ---- Scores: 8 k16-steps over Dh=128 ----
        float sc[8][4];
#pragma unroll
        for (int nt = 0; nt < 8; nt++)
#pragma unroll
            for (int e = 0; e < 4; e++) sc[nt][e] = 0.f;

#pragma unroll
        for (int ks = 0; ks < 8; ks++) {
            const int kb = ks * 8;
            uint32_t a[4];
            {
                const uint32_t* p = &fsw[OFFW_Q + (wband + g) * QW_S + kb + tg];
                a[0] = p[0];
                a[1] = p[8 * QW_S];
                a[2] = p[4];
                a[3] = p[8 * QW_S + 4];
            }
#pragma unroll
            for (int nt = 0; nt < 8; nt++) {
                const uint32_t* pk = &fsw[offK + (nt * 8 + g) * QW_S + kb + tg];
                uint32_t bb[2] = {pk[0], pk[4]};
                mma_f16(sc[nt], a, bb);
            }
        }

        // Causal mask (only the diagonal tile is partial)
        const int k0 = i * FBKV;
        if (k0 + FBKV - 1 > q0) {
#pragma unroll
            for (int nt = 0; nt < 8; nt++)
#pragma unroll
                for (int e = 0; e < 4; e++) {
                    const int qg = q0 + wband + g + ((e >> 1) << 3);
                    const int kg = k0 + nt * 8 + tg * 2 + (e & 1);
                    if (kg > qg) sc[nt][e] = -1e30f;
                }
        }

        // ---- Online softmax ----
        float corr[2];
#pragma unroll
        for (int r2 = 0; r2 < 2; r2++) {
            float tm = -1e30f;
#pragma unroll
            for (int nt = 0; nt < 8; nt++)
                tm = fmaxf(tm, fmaxf(sc[nt][r2 * 2], sc[nt][r2 * 2 + 1]));
            tm = fmaxf(tm, __shfl_xor_sync(0xffffffffu, tm, 1));
            tm = fmaxf(tm, __shfl_xor_sync(0xffffffffu, tm, 2));
            const float mn = fmaxf(m[r2], tm);
            corr[r2] = fexp(m[r2] - mn);
            m[r2] = mn;
            float s2 = 0.f;
            const int prow = OFFW_P + (wband + g + r2 * 8) * VW_S;
#pragma unroll
            for (int nt = 0; nt < 8; nt++) {
                float p0 = fexp(sc[nt][r2 * 2]     - mn);
                float p1 = fexp(sc[nt][r2 * 2 + 1] - mn);
                __half2 hp = __floats2half2_rn(p0, p1);
                float2 pr = __half22float2(hp);   // sum the ROUNDED values
                s2 += pr.x + pr.y;
                fsw[prow + nt * 4 + tg] = *(uint32_t*)&hp;
            }
            s2 += __shfl_xor_sync(0xffffffffu, s2, 1);
            s2 += __shfl_xor_sync(0xffffffffu, s2, 2);
            l[r2] = l[r2] * corr[r2] + s2;
        }

#pragma unroll
        for (int nt = 0; nt < 16; nt++) {
            O[nt][0] *= corr[0]; O[nt][1] *= corr[0];
            O[nt][2] *= corr[1]; O[nt][3] *= corr[1];
        }
        __syncwarp();   // own-warp P rows visible to own warp

        // ---- PV: 4 k16-steps over BKV=64 ----
#pragma unroll
        for (int ks = 0; ks < 4; ks++) {
            const int kb = ks * 8;
            uint32_t a[4];
            {
                const uint32_t* p = &fsw[OFFW_P + (wband + g) * VW_S + kb + tg];
                a[0] = p[0];
                a[1] = p[8 * VW_S];
                a[2] = p[4];
                a[3] = p[8 * VW_S + 4];
            }
#pragma unroll
            for (int nt = 0; nt < 16; nt++) {
                const uint32_t* pv = &fsw[offV + (nt * 8 + g) * VW_S + kb + tg];
                uint32_t bb[2] = {pv[0], pv[4]};
                mma_f16(O[nt], a, bb);
            }
        }
    }

    // ---- Write output as fp16 (feeds the O-projection GEMM) ----
    const float inv0 = 1.f / l[0];
    const float inv1 = 1.f / l[1];
    const int row0 = q0 + wband + g;
    __half* base0 = ctx + (((size_t)b * Sq + row0) * HQn + h) * Dh;
    __half* base1 = base0 + (size_t)8 * HQn * Dh;
#pragma unroll
    for (int nt = 0; nt < 16; nt++) {
        const int col = nt * 8 + tg * 2;
        *(__half2*)&base0[col] = __floats2half2_rn(O[nt][0] * inv0,
                                                   O[nt][1] * inv0);
        *(__half2*)&base1[col] = __floats2half2_rn(O[nt][2] * inv1,
                                                   O[nt][3] * inv1);
    }
}

// ---------------------------------------------------------------------------
// Launch
// ---------------------------------------------------------------------------
extern "C" void kernel_launch(void* const* d_in, const int* in_sizes, int n_in,
                              void* d_out, int out_size) {
    const float* hidden = (const float*)d_in[0];
    const float* cosb   = (const float*)d_in[1];
    const float* sinb   = (const float*)d_in[2];
    const float* Wq = (const float*)d_in[4];
    const float* Wk = (const float*)d_in[5];
    const float* Wv = (const float*)d_in[6];
    const float* Wo = (const float*)d_in[7];
    const float* qw = (const float*)d_in[8];
    const float* kw = (const float*)d_in[9];
    float* out = (float*)d_out;

    __half *qb, *kb, *vb, *cb, *hidH, *wqkvT, *woT, *vtb;
    cudaGetSymbolAddress((void**)&qb, g_qH);
    cudaGetSymbolAddress((void**)&kb, g_kH);
    cudaGetSymbolAddress((void**)&vb, g_vH);
    cudaGetSymbolAddress((void**)&cb, g_ctxH);
    cudaGetSymbolAddress((void**)&hidH, g_hidH);
    cudaGetSymbolAddress((void**)&wqkvT, g_WqkvT);
    cudaGetSymbolAddress((void**)&woT, g_WoT);
    cudaGetSymbolAddress((void**)&vtb, g_vT);

    const int M = Bq * Sq;  // 4096
    const float scale = 0.088388347648318447f;  // 1/sqrt(128)

    // Convert hidden states to fp16
    cvt_half_kernel<<<(M * Hd / 4 + 255) / 256, 256>>>(
        (const float4*)hidden, (__half2*)hidH, M * Hd / 4);

    // All weight transposes (one launch)
    transpose_all_kernel<<<dim3(64, 64, 4), dim3(32, 8)>>>(
        Wq, Wk, Wv, Wo, wqkvT, woT);

    cudaFuncSetAttribute((const void*)gemm_f16<1, __half>,
                         cudaFuncAttributeMaxDynamicSharedMemorySize, GEMM_SMEM);
    cudaFuncSetAttribute((const void*)gemm_f16<0, float>,
                         cudaFuncAttributeMaxDynamicSharedMemorySize, GEMM_SMEM);

    // Fused QKV projection (fp16 out)
    gemm_f16<1, __half><<<dim3(24, 32), 256, GEMM_SMEM>>>(
        hidH, wqkvT, Hd, qb, kb, vb);

    // RMSNorm + RoPE for q AND k in one launch (q pre-scaled by 1/sqrt(d))
    rmsnorm_rope2_kernel<<<(NQROWS + NKROWS) / 8, 256>>>(
        qb, kb, qw, kw, cosb, sinb, scale);

    // V transpose
    vtrans_kernel<<<dim3(4, 64, Bq * HKVn), dim3(32, 8)>>>(vb, vtb);

    // Flash attention (FBQ=64, 128 threads, occupancy 2)
    cudaFuncSetAttribute(flash_mma_kernel,
                         cudaFuncAttributeMaxDynamicSharedMemorySize, FLASH_SMEM);
    flash_mma_kernel<<<dim3(Sq / FBQ, Bq * HQn), 128, FLASH_SMEM>>>(
        qb, kb, vtb, cb);

    // Output projection (fp32 out)
    gemm_f16<0, float><<<dim3(16, 32), 256, GEMM_SMEM>>>(
        cb, woT, HQn * Dh, out, nullptr, nullptr);
}